// round 1
// baseline (speedup 1.0000x reference)
#include <cuda_runtime.h>

#define NN   100000
#define NE   1600000
#define ET   (NE + NN)
#define NPAD 100096   // multiple of 64 for guard-free GEMM tiles

// ---------------- scratch (device globals; no allocations) ----------------
__device__ int   g_deg[NN];
__device__ int   g_rowptr[NN + 1];
__device__ int   g_cursor[NN];
__device__ int   g_srcs[ET];
__device__ float g_h[NPAD * 128];     // transformed features (reused both layers)
__device__ float g_es[NN * 2];
__device__ float g_ed[NN * 2];
__device__ float g_out1[NPAD * 128];  // layer-1 output (relu'd, concat heads)
__device__ float g_out2[NN * 64];     // layer-2 output (head mean)

// ---------------- CSR build ----------------
__global__ void k_init_deg() {
    int i = blockIdx.x * blockDim.x + threadIdx.x;
    if (i < NN) g_deg[i] = 1;  // self-loop
}

__global__ void k_count(const int* __restrict__ ei) {
    int i = blockIdx.x * blockDim.x + threadIdx.x;
    if (i < NE) atomicAdd(&g_deg[ei[NE + i]], 1);  // dst = ei[1][i]
}

__global__ void k_scan() {  // single block, 1024 threads: exclusive scan of deg
    __shared__ int sh[1024];
    __shared__ int carry_s;
    if (threadIdx.x == 0) { carry_s = 0; g_rowptr[0] = 0; }
    __syncthreads();
    for (int base = 0; base < NN; base += 1024) {
        int i = base + threadIdx.x;
        int v = (i < NN) ? g_deg[i] : 0;
        sh[threadIdx.x] = v;
        __syncthreads();
        for (int off = 1; off < 1024; off <<= 1) {
            int t = (threadIdx.x >= off) ? sh[threadIdx.x - off] : 0;
            __syncthreads();
            sh[threadIdx.x] += t;
            __syncthreads();
        }
        int incl = carry_s + sh[threadIdx.x];
        if (i < NN) { g_rowptr[i + 1] = incl; g_cursor[i] = incl - v; }
        __syncthreads();
        if (threadIdx.x == 1023) carry_s = incl;
        __syncthreads();
    }
}

__global__ void k_scatter(const int* __restrict__ ei) {
    int i = blockIdx.x * blockDim.x + threadIdx.x;
    if (i < NE) {
        int s = ei[i], d = ei[NE + i];
        int pos = atomicAdd(&g_cursor[d], 1);
        g_srcs[pos] = s;
    } else if (i < ET) {
        int n = i - NE;
        int pos = atomicAdd(&g_cursor[n], 1);
        g_srcs[pos] = n;
    }
}

// ---------------- layer 1 transform + attention scores ----------------
// h = x @ W1 ([N,7]@[7,128]); es = sum_c h*a_src per head; ed likewise.
__global__ void k_transform1(const float* __restrict__ x, const float* __restrict__ W1,
                             const float* __restrict__ as, const float* __restrict__ ad) {
    int n = blockIdx.x;
    int tid = threadIdx.x;  // 128 threads
    __shared__ float sx[7];
    if (tid < 7) sx[tid] = x[n * 7 + tid];
    __syncthreads();
    float acc = 0.f;
#pragma unroll
    for (int k = 0; k < 7; k++) acc += sx[k] * __ldg(&W1[k * 128 + tid]);
    g_h[n * 128 + tid] = acc;

    float ps = acc * __ldg(&as[tid]);
    float pd = acc * __ldg(&ad[tid]);
#pragma unroll
    for (int off = 16; off; off >>= 1) {
        ps += __shfl_xor_sync(0xffffffffu, ps, off);
        pd += __shfl_xor_sync(0xffffffffu, pd, off);
    }
    __shared__ float red[4][2];
    int w = tid >> 5;
    if ((tid & 31) == 0) { red[w][0] = ps; red[w][1] = pd; }
    __syncthreads();
    if (tid == 0)       { g_es[2 * n]     = red[0][0] + red[1][0]; g_ed[2 * n]     = red[0][1] + red[1][1]; }
    else if (tid == 64) { g_es[2 * n + 1] = red[2][0] + red[3][0]; g_ed[2 * n + 1] = red[2][1] + red[3][1]; }
}

// ---------------- attention scores for layer 2 (h already in g_h) ----------------
__global__ void k_score2(const float* __restrict__ as, const float* __restrict__ ad) {
    int n = blockIdx.x;
    int tid = threadIdx.x;
    float acc = g_h[n * 128 + tid];
    float ps = acc * __ldg(&as[tid]);
    float pd = acc * __ldg(&ad[tid]);
#pragma unroll
    for (int off = 16; off; off >>= 1) {
        ps += __shfl_xor_sync(0xffffffffu, ps, off);
        pd += __shfl_xor_sync(0xffffffffu, pd, off);
    }
    __shared__ float red[4][2];
    int w = tid >> 5;
    if ((tid & 31) == 0) { red[w][0] = ps; red[w][1] = pd; }
    __syncthreads();
    if (tid == 0)       { g_es[2 * n]     = red[0][0] + red[1][0]; g_ed[2 * n]     = red[0][1] + red[1][1]; }
    else if (tid == 64) { g_es[2 * n + 1] = red[2][0] + red[3][0]; g_ed[2 * n + 1] = red[2][1] + red[3][1]; }
}

// ---------------- segment-softmax + aggregation, 1 warp per dst node ----------------
// LAYER==1: out1[n,128] = relu(agg/s + b1)     (concat heads)
// LAYER==2: out2[n,64]  = 0.5*(agg0/s0 + agg1/s1) + b2   (mean heads)
template <int LAYER>
__global__ void k_agg(const float* __restrict__ bias) {
    int gw = (blockIdx.x * blockDim.x + threadIdx.x) >> 5;
    if (gw >= NN) return;
    int n = gw;
    int lane = threadIdx.x & 31;
    int head = lane >> 4;
    int beg = g_rowptr[n], end = g_rowptr[n + 1];
    float ed0 = g_ed[2 * n], ed1 = g_ed[2 * n + 1];

    // pass 1: online softmax (max + rescaled sum), lane-strided over edges
    float m0 = -3e38f, s0 = 0.f, m1 = -3e38f, s1 = 0.f;
    for (int j = beg + lane; j < end; j += 32) {
        int src = g_srcs[j];
        float e0 = g_es[2 * src] + ed0;     e0 = e0 > 0.f ? e0 : 0.2f * e0;
        float e1 = g_es[2 * src + 1] + ed1; e1 = e1 > 0.f ? e1 : 0.2f * e1;
        if (e0 > m0) { s0 = s0 * __expf(m0 - e0) + 1.f; m0 = e0; } else s0 += __expf(e0 - m0);
        if (e1 > m1) { s1 = s1 * __expf(m1 - e1) + 1.f; m1 = e1; } else s1 += __expf(e1 - m1);
    }
#pragma unroll
    for (int off = 16; off; off >>= 1) {
        float mo = __shfl_xor_sync(0xffffffffu, m0, off);
        float so = __shfl_xor_sync(0xffffffffu, s0, off);
        float mn = fmaxf(m0, mo);
        s0 = s0 * __expf(m0 - mn) + so * __expf(mo - mn); m0 = mn;
        mo = __shfl_xor_sync(0xffffffffu, m1, off);
        so = __shfl_xor_sync(0xffffffffu, s1, off);
        mn = fmaxf(m1, mo);
        s1 = s1 * __expf(m1 - mn) + so * __expf(mo - mn); m1 = mn;
    }

    float myEd = head ? ed1 : ed0;
    float myM  = head ? m1 : m0;
    float invs = 1.f / (head ? s1 : s0);

    // pass 2: accumulate unnormalized sum_j exp(e-m)*h[src]; lane owns 4 channels
    float4 acc = make_float4(0.f, 0.f, 0.f, 0.f);
    for (int j = beg; j < end; j++) {
        int src = g_srcs[j];
        float e = g_es[2 * src + head] + myEd;
        e = e > 0.f ? e : 0.2f * e;
        float w = __expf(e - myM);
        float4 hv = *(const float4*)(g_h + src * 128 + lane * 4);
        acc.x += w * hv.x; acc.y += w * hv.y; acc.z += w * hv.z; acc.w += w * hv.w;
    }

    if (LAYER == 1) {
        int c = lane * 4;
        float4 o;
        o.x = fmaxf(acc.x * invs + __ldg(&bias[c + 0]), 0.f);
        o.y = fmaxf(acc.y * invs + __ldg(&bias[c + 1]), 0.f);
        o.z = fmaxf(acc.z * invs + __ldg(&bias[c + 2]), 0.f);
        o.w = fmaxf(acc.w * invs + __ldg(&bias[c + 3]), 0.f);
        *(float4*)&g_out1[n * 128 + c] = o;
    } else {
        acc.x *= invs; acc.y *= invs; acc.z *= invs; acc.w *= invs;
        acc.x += __shfl_xor_sync(0xffffffffu, acc.x, 16);
        acc.y += __shfl_xor_sync(0xffffffffu, acc.y, 16);
        acc.z += __shfl_xor_sync(0xffffffffu, acc.z, 16);
        acc.w += __shfl_xor_sync(0xffffffffu, acc.w, 16);
        if (lane < 16) {
            int c = lane * 4;
            float4 o;
            o.x = 0.5f * acc.x + __ldg(&bias[c + 0]);
            o.y = 0.5f * acc.y + __ldg(&bias[c + 1]);
            o.z = 0.5f * acc.z + __ldg(&bias[c + 2]);
            o.w = 0.5f * acc.w + __ldg(&bias[c + 3]);
            *(float4*)&g_out2[n * 64 + c] = o;
        }
    }
}

// ---------------- layer 2 GEMM: g_h = g_out1 @ W2  ([NPAD,128]@[128,128]) ----------------
__global__ void k_gemm2(const float* __restrict__ W2) {
    __shared__ float sIn[64 * 128];  // 32KB: 64 input rows
    __shared__ float sW[16 * 128];   // 8KB: one k-tile of W2
    int tid = threadIdx.x;           // 256 threads
    int nbase = blockIdx.x * 64;

#pragma unroll
    for (int r = 0; r < 8; r++) {
        int idx = tid + r * 256;  // float4 index, 2048 total
        ((float4*)sIn)[idx] = ((const float4*)(g_out1 + (size_t)nbase * 128))[idx];
    }

    float acc[8][4];
#pragma unroll
    for (int m = 0; m < 8; m++) { acc[m][0] = acc[m][1] = acc[m][2] = acc[m][3] = 0.f; }
    int jq = tid & 31;   // column quad: cols 4*jq..4*jq+3
    int mg = tid >> 5;   // node group 0..7: nodes mg*8..mg*8+7
    __syncthreads();

    for (int kt = 0; kt < 8; kt++) {
#pragma unroll
        for (int r = 0; r < 2; r++) {
            int idx = tid + r * 256;  // 512 float4s
            ((float4*)sW)[idx] = ((const float4*)(W2 + kt * 16 * 128))[idx];
        }
        __syncthreads();
#pragma unroll
        for (int k = 0; k < 16; k++) {
            float4 w = *(float4*)&sW[k * 128 + jq * 4];
#pragma unroll
            for (int m = 0; m < 8; m++) {
                float v = sIn[(mg * 8 + m) * 128 + kt * 16 + k];
                acc[m][0] += v * w.x; acc[m][1] += v * w.y;
                acc[m][2] += v * w.z; acc[m][3] += v * w.w;
            }
        }
        __syncthreads();
    }
#pragma unroll
    for (int m = 0; m < 8; m++) {
        int n = nbase + mg * 8 + m;
        *(float4*)&g_h[(size_t)n * 128 + jq * 4] =
            make_float4(acc[m][0], acc[m][1], acc[m][2], acc[m][3]);
    }
}

// ---------------- classifier: relu(out2@Wc1+bc1)@Wc2+bc2 -> d_out ----------------
__global__ void k_classifier(const float* __restrict__ Wc1, const float* __restrict__ bc1,
                             const float* __restrict__ Wc2, const float* __restrict__ bc2,
                             float* __restrict__ out) {
    __shared__ float sW1[64 * 64];  // 16KB
    __shared__ float sW2[64 * 4];
    __shared__ float sb1[64];
    __shared__ float sb2[4];
    __shared__ float sv[16 * 64];   // 16 input rows
    __shared__ float sh2[16 * 64];  // hidden
    int tid = threadIdx.x;          // 256
    int nbase = blockIdx.x * 16;

#pragma unroll
    for (int r = 0; r < 4; r++)
        ((float4*)sW1)[tid + r * 256] = ((const float4*)Wc1)[tid + r * 256];
    if (tid < 64) {
        ((float4*)sW2)[tid] = ((const float4*)Wc2)[tid];
        sb1[tid] = bc1[tid];
    }
    if (tid < 4) sb2[tid] = bc2[tid];
    ((float4*)sv)[tid] = ((const float4*)(g_out2 + (size_t)nbase * 64))[tid];
    __syncthreads();

    // stage 1: hidden = relu(v @ Wc1 + bc1); thread = (node, col-quad)
    {
        int node = tid >> 4;
        int cq = tid & 15;
        float a0 = sb1[cq * 4], a1 = sb1[cq * 4 + 1], a2 = sb1[cq * 4 + 2], a3 = sb1[cq * 4 + 3];
#pragma unroll
        for (int k = 0; k < 64; k++) {
            float v = sv[node * 64 + k];
            float4 w = *(float4*)&sW1[k * 64 + cq * 4];
            a0 += v * w.x; a1 += v * w.y; a2 += v * w.z; a3 += v * w.w;
        }
        *(float4*)&sh2[node * 64 + cq * 4] =
            make_float4(fmaxf(a0, 0.f), fmaxf(a1, 0.f), fmaxf(a2, 0.f), fmaxf(a3, 0.f));
    }
    __syncthreads();

    // stage 2: out = hidden @ Wc2 + bc2
    if (tid < 64) {
        int n2 = tid >> 2, o = tid & 3;
        float a = sb2[o];
#pragma unroll
        for (int k = 0; k < 64; k++) a += sh2[n2 * 64 + k] * sW2[k * 4 + o];
        out[(size_t)(nbase + n2) * 4 + o] = a;
    }
}

// ---------------- launch ----------------
extern "C" void kernel_launch(void* const* d_in, const int* in_sizes, int n_in,
                              void* d_out, int out_size) {
    const float* x   = (const float*)d_in[0];
    const int*   ei  = (const int*)d_in[1];
    const float* W1  = (const float*)d_in[2];
    const float* as1 = (const float*)d_in[3];
    const float* ad1 = (const float*)d_in[4];
    const float* b1  = (const float*)d_in[5];
    const float* W2  = (const float*)d_in[6];
    const float* as2 = (const float*)d_in[7];
    const float* ad2 = (const float*)d_in[8];
    const float* b2  = (const float*)d_in[9];
    const float* Wc1 = (const float*)d_in[10];
    const float* bc1 = (const float*)d_in[11];
    const float* Wc2 = (const float*)d_in[12];
    const float* bc2 = (const float*)d_in[13];
    float* out = (float*)d_out;

    // CSR build (dst-major, includes self-loops)
    k_init_deg<<<(NN + 255) / 256, 256>>>();
    k_count<<<(NE + 255) / 256, 256>>>(ei);
    k_scan<<<1, 1024>>>();
    k_scatter<<<(ET + 255) / 256, 256>>>(ei);

    // layer 1
    k_transform1<<<NN, 128>>>(x, W1, as1, ad1);
    k_agg<1><<<(NN + 7) / 8, 256>>>(b1);

    // layer 2
    k_gemm2<<<NPAD / 64, 256>>>(W2);
    k_score2<<<NN, 128>>>(as2, ad2);
    k_agg<2><<<(NN + 7) / 8, 256>>>(b2);

    // classifier
    k_classifier<<<NN / 16, 256>>>(Wc1, bc1, Wc2, bc2, out);
}

// round 2
// speedup vs baseline: 1.3269x; 1.3269x over previous
#include <cuda_runtime.h>

#define NN   100000
#define NE   1600000
#define ET   (NE + NN)
#define NPAD 100096   // multiple of 64 for guard-free GEMM tiles
#define SCAN_BLKS ((NN + 1023) / 1024)   // 98

// ---------------- scratch (device globals; no allocations) ----------------
__device__ int   g_deg[NN];
__device__ int   g_rowptr[NN + 1];
__device__ int   g_cursor[NN];
__device__ int   g_srcs[ET];
__device__ int   g_part[SCAN_BLKS];
__device__ int   g_partscan[SCAN_BLKS];
__device__ float g_h[NPAD * 128];     // transformed features (reused both layers)
__device__ float g_es[NN * 2];
__device__ float g_ed[NN * 2];
__device__ float g_out1[NPAD * 128];  // layer-1 output (relu'd, concat heads)
__device__ float g_out2[NN * 64];     // layer-2 output (head mean)

// ---------------- CSR build ----------------
__global__ void k_init_deg() {
    int i = blockIdx.x * blockDim.x + threadIdx.x;
    if (i < NN) g_deg[i] = 1;  // self-loop
}

__global__ void k_count(const int* __restrict__ ei) {
    int i = blockIdx.x * blockDim.x + threadIdx.x;
    if (i < NE) atomicAdd(&g_deg[ei[NE + i]], 1);  // dst = ei[1][i]
}

// two-level scan: partial sums per 1024-elem block
__global__ void k_part() {
    __shared__ int sh[256];
    int base = blockIdx.x * 1024;
    int t = threadIdx.x;
    int idx = base + t * 4;
    int s = 0;
#pragma unroll
    for (int r = 0; r < 4; r++) s += (idx + r < NN) ? g_deg[idx + r] : 0;
    sh[t] = s;
    __syncthreads();
    for (int off = 128; off; off >>= 1) {
        if (t < off) sh[t] += sh[t + off];
        __syncthreads();
    }
    if (t == 0) g_part[blockIdx.x] = sh[0];
}

__global__ void k_scanpart() {  // 1 block, 128 threads: exclusive scan of 98 partials
    __shared__ int sh[128];
    int t = threadIdx.x;
    int v = (t < SCAN_BLKS) ? g_part[t] : 0;
    sh[t] = v;
    __syncthreads();
    for (int off = 1; off < 128; off <<= 1) {
        int tv = (t >= off) ? sh[t - off] : 0;
        __syncthreads();
        sh[t] += tv;
        __syncthreads();
    }
    if (t < SCAN_BLKS) g_partscan[t] = sh[t] - v;
    if (t == 0) g_rowptr[NN] = ET;
}

__global__ void k_scanfinal() {  // 98 blocks × 256 threads, 4 elems/thread
    __shared__ int sh[256];
    int base = blockIdx.x * 1024;
    int t = threadIdx.x;
    int idx = base + t * 4;
    int v[4];
    int s = 0;
#pragma unroll
    for (int r = 0; r < 4; r++) {
        v[r] = (idx + r < NN) ? g_deg[idx + r] : 0;
        s += v[r];
    }
    sh[t] = s;
    __syncthreads();
    for (int off = 1; off < 256; off <<= 1) {
        int tv = (t >= off) ? sh[t - off] : 0;
        __syncthreads();
        sh[t] += tv;
        __syncthreads();
    }
    int excl = sh[t] - s + g_partscan[blockIdx.x];
#pragma unroll
    for (int r = 0; r < 4; r++) {
        if (idx + r < NN) {
            g_rowptr[idx + r] = excl;
            g_cursor[idx + r] = excl;
            excl += v[r];
        }
    }
}

__global__ void k_scatter(const int* __restrict__ ei) {
    int i = blockIdx.x * blockDim.x + threadIdx.x;
    if (i < NE) {
        int s = ei[i], d = ei[NE + i];
        int pos = atomicAdd(&g_cursor[d], 1);
        g_srcs[pos] = s;
    } else if (i < ET) {
        int n = i - NE;
        int pos = atomicAdd(&g_cursor[n], 1);
        g_srcs[pos] = n;
    }
}

// ---------------- layer 1 transform + attention scores ----------------
__global__ void k_transform1(const float* __restrict__ x, const float* __restrict__ W1,
                             const float* __restrict__ as, const float* __restrict__ ad) {
    int n = blockIdx.x;
    int tid = threadIdx.x;  // 128 threads
    __shared__ float sx[7];
    if (tid < 7) sx[tid] = x[n * 7 + tid];
    __syncthreads();
    float acc = 0.f;
#pragma unroll
    for (int k = 0; k < 7; k++) acc += sx[k] * __ldg(&W1[k * 128 + tid]);
    g_h[n * 128 + tid] = acc;

    float ps = acc * __ldg(&as[tid]);
    float pd = acc * __ldg(&ad[tid]);
#pragma unroll
    for (int off = 16; off; off >>= 1) {
        ps += __shfl_xor_sync(0xffffffffu, ps, off);
        pd += __shfl_xor_sync(0xffffffffu, pd, off);
    }
    __shared__ float red[4][2];
    int w = tid >> 5;
    if ((tid & 31) == 0) { red[w][0] = ps; red[w][1] = pd; }
    __syncthreads();
    if (tid == 0)       { g_es[2 * n]     = red[0][0] + red[1][0]; g_ed[2 * n]     = red[0][1] + red[1][1]; }
    else if (tid == 64) { g_es[2 * n + 1] = red[2][0] + red[3][0]; g_ed[2 * n + 1] = red[2][1] + red[3][1]; }
}

// ---------------- segment-softmax + aggregation, 1 warp per dst node ----------------
// Chunk-0 (first 32 edges) is register-cached in pass 1 and replayed via SHFL
// broadcast in pass 2 (weights precomputed). Overflow edges use a fallback path.
template <int LAYER>
__global__ void k_agg(const float* __restrict__ bias) {
    int gw = (blockIdx.x * blockDim.x + threadIdx.x) >> 5;
    if (gw >= NN) return;
    int n = gw;
    int lane = threadIdx.x & 31;
    int head = lane >> 4;
    int beg = g_rowptr[n], end = g_rowptr[n + 1];
    float ed0 = g_ed[2 * n], ed1 = g_ed[2 * n + 1];

    // --- pass 1: chunk-0 cached + online softmax over all edges ---
    float m0 = -3e38f, s0 = 0.f, m1 = -3e38f, s1 = 0.f;
    int   src_c = 0;
    float e0_c = -3e38f, e1_c = -3e38f;
    {
        int j = beg + lane;
        if (j < end) {
            src_c = g_srcs[j];
            float2 es = *(const float2*)(g_es + 2 * src_c);
            float e0 = es.x + ed0; e0 = e0 > 0.f ? e0 : 0.2f * e0;
            float e1 = es.y + ed1; e1 = e1 > 0.f ? e1 : 0.2f * e1;
            e0_c = e0; e1_c = e1;
            m0 = e0; s0 = 1.f;
            m1 = e1; s1 = 1.f;
        }
    }
    for (int j = beg + 32 + lane; j < end; j += 32) {
        int src = g_srcs[j];
        float2 es = *(const float2*)(g_es + 2 * src);
        float e0 = es.x + ed0; e0 = e0 > 0.f ? e0 : 0.2f * e0;
        float e1 = es.y + ed1; e1 = e1 > 0.f ? e1 : 0.2f * e1;
        if (e0 > m0) { s0 = s0 * __expf(m0 - e0) + 1.f; m0 = e0; } else s0 += __expf(e0 - m0);
        if (e1 > m1) { s1 = s1 * __expf(m1 - e1) + 1.f; m1 = e1; } else s1 += __expf(e1 - m1);
    }
#pragma unroll
    for (int off = 16; off; off >>= 1) {
        float mo = __shfl_xor_sync(0xffffffffu, m0, off);
        float so = __shfl_xor_sync(0xffffffffu, s0, off);
        float mn = fmaxf(m0, mo);
        s0 = s0 * __expf(m0 - mn) + so * __expf(mo - mn); m0 = mn;
        mo = __shfl_xor_sync(0xffffffffu, m1, off);
        so = __shfl_xor_sync(0xffffffffu, s1, off);
        mn = fmaxf(m1, mo);
        s1 = s1 * __expf(m1 - mn) + so * __expf(mo - mn); m1 = mn;
    }

    float myM  = head ? m1 : m0;
    float myEd = head ? ed1 : ed0;
    float invs = 1.f / (head ? s1 : s0);

    // per-lane precomputed unnormalized weights for chunk-0 (0 for invalid lanes)
    float w0_c = __expf(e0_c - m0);
    float w1_c = __expf(e1_c - m1);

    // --- pass 2: chunk-0 via SHFL broadcast, overflow via fallback ---
    float4 acc = make_float4(0.f, 0.f, 0.f, 0.f);
    int cnt0 = end - beg; if (cnt0 > 32) cnt0 = 32;
    for (int jj = 0; jj < cnt0; jj++) {
        int   src = __shfl_sync(0xffffffffu, src_c, jj);
        float w0  = __shfl_sync(0xffffffffu, w0_c, jj);
        float w1  = __shfl_sync(0xffffffffu, w1_c, jj);
        float w   = head ? w1 : w0;
        float4 hv = *(const float4*)(g_h + (size_t)src * 128 + lane * 4);
        acc.x += w * hv.x; acc.y += w * hv.y; acc.z += w * hv.z; acc.w += w * hv.w;
    }
    for (int j = beg + 32; j < end; j++) {
        int src = g_srcs[j];
        float e = g_es[2 * src + head] + myEd;
        e = e > 0.f ? e : 0.2f * e;
        float w = __expf(e - myM);
        float4 hv = *(const float4*)(g_h + (size_t)src * 128 + lane * 4);
        acc.x += w * hv.x; acc.y += w * hv.y; acc.z += w * hv.z; acc.w += w * hv.w;
    }

    if (LAYER == 1) {
        int c = lane * 4;
        float4 o;
        o.x = fmaxf(acc.x * invs + __ldg(&bias[c + 0]), 0.f);
        o.y = fmaxf(acc.y * invs + __ldg(&bias[c + 1]), 0.f);
        o.z = fmaxf(acc.z * invs + __ldg(&bias[c + 2]), 0.f);
        o.w = fmaxf(acc.w * invs + __ldg(&bias[c + 3]), 0.f);
        *(float4*)&g_out1[(size_t)n * 128 + c] = o;
    } else {
        acc.x *= invs; acc.y *= invs; acc.z *= invs; acc.w *= invs;
        acc.x += __shfl_xor_sync(0xffffffffu, acc.x, 16);
        acc.y += __shfl_xor_sync(0xffffffffu, acc.y, 16);
        acc.z += __shfl_xor_sync(0xffffffffu, acc.z, 16);
        acc.w += __shfl_xor_sync(0xffffffffu, acc.w, 16);
        if (lane < 16) {
            int c = lane * 4;
            float4 o;
            o.x = 0.5f * acc.x + __ldg(&bias[c + 0]);
            o.y = 0.5f * acc.y + __ldg(&bias[c + 1]);
            o.z = 0.5f * acc.z + __ldg(&bias[c + 2]);
            o.w = 0.5f * acc.w + __ldg(&bias[c + 3]);
            *(float4*)&g_out2[(size_t)n * 64 + c] = o;
        }
    }
}

// ---------------- layer 2 GEMM + fused attention scores ----------------
// g_h = g_out1 @ W2 ([NPAD,128]@[128,128]); es/ed computed from the
// register-resident result (no re-read of g_h).
__global__ void k_gemm2(const float* __restrict__ W2,
                        const float* __restrict__ as, const float* __restrict__ ad) {
    __shared__ float sIn[64 * 128];  // 32KB: 64 input rows
    __shared__ float sW[16 * 128];   // 8KB: one k-tile of W2
    int tid = threadIdx.x;           // 256 threads
    int nbase = blockIdx.x * 64;

#pragma unroll
    for (int r = 0; r < 8; r++) {
        int idx = tid + r * 256;  // float4 index, 2048 total
        ((float4*)sIn)[idx] = ((const float4*)(g_out1 + (size_t)nbase * 128))[idx];
    }

    float acc[8][4];
#pragma unroll
    for (int m = 0; m < 8; m++) { acc[m][0] = acc[m][1] = acc[m][2] = acc[m][3] = 0.f; }
    int jq = tid & 31;   // column quad: cols 4*jq..4*jq+3
    int mg = tid >> 5;   // node group 0..7: nodes mg*8..mg*8+7 (one warp per mg)
    __syncthreads();

    for (int kt = 0; kt < 8; kt++) {
#pragma unroll
        for (int r = 0; r < 2; r++) {
            int idx = tid + r * 256;  // 512 float4s
            ((float4*)sW)[idx] = ((const float4*)(W2 + kt * 16 * 128))[idx];
        }
        __syncthreads();
#pragma unroll
        for (int k = 0; k < 16; k++) {
            float4 w = *(float4*)&sW[k * 128 + jq * 4];
#pragma unroll
            for (int m = 0; m < 8; m++) {
                float v = sIn[(mg * 8 + m) * 128 + kt * 16 + k];
                acc[m][0] += v * w.x; acc[m][1] += v * w.y;
                acc[m][2] += v * w.z; acc[m][3] += v * w.w;
            }
        }
        __syncthreads();
    }

    // store h
#pragma unroll
    for (int m = 0; m < 8; m++) {
        int nn = nbase + mg * 8 + m;
        *(float4*)&g_h[(size_t)nn * 128 + jq * 4] =
            make_float4(acc[m][0], acc[m][1], acc[m][2], acc[m][3]);
    }

    // fused attention scores: lanes 0-15 cover cols 0-63 (head0), 16-31 head1
    float4 av = *(const float4*)(as + jq * 4);
    float4 dv = *(const float4*)(ad + jq * 4);
    float ps[8], pd[8];
#pragma unroll
    for (int m = 0; m < 8; m++) {
        ps[m] = acc[m][0] * av.x + acc[m][1] * av.y + acc[m][2] * av.z + acc[m][3] * av.w;
        pd[m] = acc[m][0] * dv.x + acc[m][1] * dv.y + acc[m][2] * dv.z + acc[m][3] * dv.w;
    }
#pragma unroll
    for (int off = 8; off; off >>= 1) {
#pragma unroll
        for (int m = 0; m < 8; m++) {
            ps[m] += __shfl_xor_sync(0xffffffffu, ps[m], off);
            pd[m] += __shfl_xor_sync(0xffffffffu, pd[m], off);
        }
    }
    if (jq == 0 || jq == 16) {
        int h = jq >> 4;
#pragma unroll
        for (int m = 0; m < 8; m++) {
            int nn = nbase + mg * 8 + m;
            if (nn < NN) {
                g_es[2 * nn + h] = ps[m];
                g_ed[2 * nn + h] = pd[m];
            }
        }
    }
}

// ---------------- classifier: relu(out2@Wc1+bc1)@Wc2+bc2 -> d_out ----------------
__global__ void k_classifier(const float* __restrict__ Wc1, const float* __restrict__ bc1,
                             const float* __restrict__ Wc2, const float* __restrict__ bc2,
                             float* __restrict__ out) {
    __shared__ float sW1[64 * 64];  // 16KB
    __shared__ float sW2[64 * 4];
    __shared__ float sb1[64];
    __shared__ float sb2[4];
    __shared__ float sv[16 * 64];   // 16 input rows
    __shared__ float sh2[16 * 64];  // hidden
    int tid = threadIdx.x;          // 256
    int nbase = blockIdx.x * 16;

#pragma unroll
    for (int r = 0; r < 4; r++)
        ((float4*)sW1)[tid + r * 256] = ((const float4*)Wc1)[tid + r * 256];
    if (tid < 64) {
        ((float4*)sW2)[tid] = ((const float4*)Wc2)[tid];
        sb1[tid] = bc1[tid];
    }
    if (tid < 4) sb2[tid] = bc2[tid];
    ((float4*)sv)[tid] = ((const float4*)(g_out2 + (size_t)nbase * 64))[tid];
    __syncthreads();

    {
        int node = tid >> 4;
        int cq = tid & 15;
        float a0 = sb1[cq * 4], a1 = sb1[cq * 4 + 1], a2 = sb1[cq * 4 + 2], a3 = sb1[cq * 4 + 3];
#pragma unroll
        for (int k = 0; k < 64; k++) {
            float v = sv[node * 64 + k];
            float4 w = *(float4*)&sW1[k * 64 + cq * 4];
            a0 += v * w.x; a1 += v * w.y; a2 += v * w.z; a3 += v * w.w;
        }
        *(float4*)&sh2[node * 64 + cq * 4] =
            make_float4(fmaxf(a0, 0.f), fmaxf(a1, 0.f), fmaxf(a2, 0.f), fmaxf(a3, 0.f));
    }
    __syncthreads();

    if (tid < 64) {
        int n2 = tid >> 2, o = tid & 3;
        float a = sb2[o];
#pragma unroll
        for (int k = 0; k < 64; k++) a += sh2[n2 * 64 + k] * sW2[k * 4 + o];
        out[(size_t)(nbase + n2) * 4 + o] = a;
    }
}

// ---------------- launch ----------------
extern "C" void kernel_launch(void* const* d_in, const int* in_sizes, int n_in,
                              void* d_out, int out_size) {
    const float* x   = (const float*)d_in[0];
    const int*   ei  = (const int*)d_in[1];
    const float* W1  = (const float*)d_in[2];
    const float* as1 = (const float*)d_in[3];
    const float* ad1 = (const float*)d_in[4];
    const float* b1  = (const float*)d_in[5];
    const float* W2  = (const float*)d_in[6];
    const float* as2 = (const float*)d_in[7];
    const float* ad2 = (const float*)d_in[8];
    const float* b2  = (const float*)d_in[9];
    const float* Wc1 = (const float*)d_in[10];
    const float* bc1 = (const float*)d_in[11];
    const float* Wc2 = (const float*)d_in[12];
    const float* bc2 = (const float*)d_in[13];
    float* out = (float*)d_out;

    // CSR build (dst-major, includes self-loops)
    k_init_deg<<<(NN + 255) / 256, 256>>>();
    k_count<<<(NE + 255) / 256, 256>>>(ei);
    k_part<<<SCAN_BLKS, 256>>>();
    k_scanpart<<<1, 128>>>();
    k_scanfinal<<<SCAN_BLKS, 256>>>();
    k_scatter<<<(ET + 255) / 256, 256>>>(ei);

    // layer 1
    k_transform1<<<NN, 128>>>(x, W1, as1, ad1);
    k_agg<1><<<(NN + 7) / 8, 256>>>(b1);

    // layer 2 (GEMM with fused attention scores)
    k_gemm2<<<NPAD / 64, 256>>>(W2, as2, ad2);
    k_agg<2><<<(NN + 7) / 8, 256>>>(b2);

    // classifier
    k_classifier<<<NN / 16, 256>>>(Wc1, bc1, Wc2, bc2, out);
}

// round 3
// speedup vs baseline: 1.3989x; 1.0543x over previous
#include <cuda_runtime.h>
#include <cuda_fp16.h>

#define NN   100000
#define NE   1600000
#define ET   (NE + NN)
#define NPAD 100096   // multiple of 64 for guard-free GEMM tiles
#define SCAN_BLKS ((NN + 1023) / 1024)   // 98

// ---------------- scratch (device globals; no allocations) ----------------
__device__ int    g_deg[NN];
__device__ int    g_rowptr[NN + 1];
__device__ int    g_cursor[NN];
__device__ int    g_srcs[ET];
__device__ int    g_part[SCAN_BLKS];
__device__ int    g_partscan[SCAN_BLKS];
__device__ __half g_h[NPAD * 128];     // transformed features, fp16 (reused both layers)
__device__ float  g_es[NN * 2];
__device__ float  g_ed[NN * 2];
__device__ float  g_out1[NPAD * 128];  // layer-1 output (relu'd, concat heads), fp32
__device__ float  g_out2[NN * 64];     // layer-2 output (head mean), fp32

// ---------------- CSR build ----------------
__global__ void k_init_deg() {
    int i = blockIdx.x * blockDim.x + threadIdx.x;
    if (i < NN) g_deg[i] = 1;  // self-loop
}

__global__ void k_count(const int* __restrict__ ei) {
    int i = blockIdx.x * blockDim.x + threadIdx.x;
    if (i < NE) atomicAdd(&g_deg[ei[NE + i]], 1);  // dst = ei[1][i]
}

__global__ void k_part() {
    __shared__ int sh[256];
    int base = blockIdx.x * 1024;
    int t = threadIdx.x;
    int idx = base + t * 4;
    int s = 0;
#pragma unroll
    for (int r = 0; r < 4; r++) s += (idx + r < NN) ? g_deg[idx + r] : 0;
    sh[t] = s;
    __syncthreads();
    for (int off = 128; off; off >>= 1) {
        if (t < off) sh[t] += sh[t + off];
        __syncthreads();
    }
    if (t == 0) g_part[blockIdx.x] = sh[0];
}

__global__ void k_scanpart() {  // 1 block, 128 threads: exclusive scan of 98 partials
    __shared__ int sh[128];
    int t = threadIdx.x;
    int v = (t < SCAN_BLKS) ? g_part[t] : 0;
    sh[t] = v;
    __syncthreads();
    for (int off = 1; off < 128; off <<= 1) {
        int tv = (t >= off) ? sh[t - off] : 0;
        __syncthreads();
        sh[t] += tv;
        __syncthreads();
    }
    if (t < SCAN_BLKS) g_partscan[t] = sh[t] - v;
    if (t == 0) g_rowptr[NN] = ET;
}

__global__ void k_scanfinal() {  // 98 blocks × 256 threads, 4 elems/thread
    __shared__ int sh[256];
    int base = blockIdx.x * 1024;
    int t = threadIdx.x;
    int idx = base + t * 4;
    int v[4];
    int s = 0;
#pragma unroll
    for (int r = 0; r < 4; r++) {
        v[r] = (idx + r < NN) ? g_deg[idx + r] : 0;
        s += v[r];
    }
    sh[t] = s;
    __syncthreads();
    for (int off = 1; off < 256; off <<= 1) {
        int tv = (t >= off) ? sh[t - off] : 0;
        __syncthreads();
        sh[t] += tv;
        __syncthreads();
    }
    int excl = sh[t] - s + g_partscan[blockIdx.x];
#pragma unroll
    for (int r = 0; r < 4; r++) {
        if (idx + r < NN) {
            g_rowptr[idx + r] = excl;
            g_cursor[idx + r] = excl;
            excl += v[r];
        }
    }
}

__global__ void k_scatter(const int* __restrict__ ei) {
    int i = blockIdx.x * blockDim.x + threadIdx.x;
    if (i < NE) {
        int s = ei[i], d = ei[NE + i];
        int pos = atomicAdd(&g_cursor[d], 1);
        g_srcs[pos] = s;
    } else if (i < ET) {
        int n = i - NE;
        int pos = atomicAdd(&g_cursor[n], 1);
        g_srcs[pos] = n;
    }
}

// ---------------- layer 1 transform + attention scores ----------------
__global__ void k_transform1(const float* __restrict__ x, const float* __restrict__ W1,
                             const float* __restrict__ as, const float* __restrict__ ad) {
    int n = blockIdx.x;
    int tid = threadIdx.x;  // 128 threads
    __shared__ float sx[7];
    if (tid < 7) sx[tid] = x[n * 7 + tid];
    __syncthreads();
    float acc = 0.f;
#pragma unroll
    for (int k = 0; k < 7; k++) acc += sx[k] * __ldg(&W1[k * 128 + tid]);
    g_h[n * 128 + tid] = __float2half(acc);

    float ps = acc * __ldg(&as[tid]);
    float pd = acc * __ldg(&ad[tid]);
#pragma unroll
    for (int off = 16; off; off >>= 1) {
        ps += __shfl_xor_sync(0xffffffffu, ps, off);
        pd += __shfl_xor_sync(0xffffffffu, pd, off);
    }
    __shared__ float red[4][2];
    int w = tid >> 5;
    if ((tid & 31) == 0) { red[w][0] = ps; red[w][1] = pd; }
    __syncthreads();
    if (tid == 0)       { g_es[2 * n]     = red[0][0] + red[1][0]; g_ed[2 * n]     = red[0][1] + red[1][1]; }
    else if (tid == 64) { g_es[2 * n + 1] = red[2][0] + red[3][0]; g_ed[2 * n + 1] = red[2][1] + red[3][1]; }
}

// ---------------- segment-softmax + aggregation, 1 warp per dst node ----------------
// Single pass, no max subtraction (scores bounded: |e| < ~10 by construction).
// Each 32-edge chunk: lane loads (src, w=exp(e)); broadcast via SHFL; lane
// accumulates 4 fp16 channels of h[src] into fp32; normalize at the end.
template <int LAYER>
__global__ void k_agg(const float* __restrict__ bias) {
    int gw = (blockIdx.x * blockDim.x + threadIdx.x) >> 5;
    if (gw >= NN) return;
    int n = gw;
    int lane = threadIdx.x & 31;
    int head = lane >> 4;
    int beg = g_rowptr[n], end = g_rowptr[n + 1];
    float ed0 = g_ed[2 * n], ed1 = g_ed[2 * n + 1];

    float sw0 = 0.f, sw1 = 0.f;
    float4 acc = make_float4(0.f, 0.f, 0.f, 0.f);

    for (int base = beg; base < end; base += 32) {
        int j = base + lane;
        int src_c = 0;
        float w0_c = 0.f, w1_c = 0.f;
        if (j < end) {
            src_c = g_srcs[j];
            float2 es = *(const float2*)(g_es + 2 * src_c);
            float e0 = es.x + ed0; e0 = e0 > 0.f ? e0 : 0.2f * e0;
            float e1 = es.y + ed1; e1 = e1 > 0.f ? e1 : 0.2f * e1;
            w0_c = __expf(e0);
            w1_c = __expf(e1);
        }
        sw0 += w0_c; sw1 += w1_c;

        int cnt = end - base; if (cnt > 32) cnt = 32;
        for (int jj = 0; jj < cnt; jj++) {
            int   src = __shfl_sync(0xffffffffu, src_c, jj);
            float w0  = __shfl_sync(0xffffffffu, w0_c, jj);
            float w1  = __shfl_sync(0xffffffffu, w1_c, jj);
            float w   = head ? w1 : w0;
            uint2 u = ((const uint2*)(g_h + (size_t)src * 128))[lane];
            float2 f01 = __half22float2(*(__half2*)&u.x);
            float2 f23 = __half22float2(*(__half2*)&u.y);
            acc.x += w * f01.x; acc.y += w * f01.y;
            acc.z += w * f23.x; acc.w += w * f23.y;
        }
    }

    // warp-sum of per-lane partial weight sums
#pragma unroll
    for (int off = 16; off; off >>= 1) {
        sw0 += __shfl_xor_sync(0xffffffffu, sw0, off);
        sw1 += __shfl_xor_sync(0xffffffffu, sw1, off);
    }
    float invs = 1.f / (head ? sw1 : sw0);

    if (LAYER == 1) {
        int c = lane * 4;
        float4 o;
        o.x = fmaxf(acc.x * invs + __ldg(&bias[c + 0]), 0.f);
        o.y = fmaxf(acc.y * invs + __ldg(&bias[c + 1]), 0.f);
        o.z = fmaxf(acc.z * invs + __ldg(&bias[c + 2]), 0.f);
        o.w = fmaxf(acc.w * invs + __ldg(&bias[c + 3]), 0.f);
        *(float4*)&g_out1[(size_t)n * 128 + c] = o;
    } else {
        acc.x *= invs; acc.y *= invs; acc.z *= invs; acc.w *= invs;
        acc.x += __shfl_xor_sync(0xffffffffu, acc.x, 16);
        acc.y += __shfl_xor_sync(0xffffffffu, acc.y, 16);
        acc.z += __shfl_xor_sync(0xffffffffu, acc.z, 16);
        acc.w += __shfl_xor_sync(0xffffffffu, acc.w, 16);
        if (lane < 16) {
            int c = lane * 4;
            float4 o;
            o.x = 0.5f * acc.x + __ldg(&bias[c + 0]);
            o.y = 0.5f * acc.y + __ldg(&bias[c + 1]);
            o.z = 0.5f * acc.z + __ldg(&bias[c + 2]);
            o.w = 0.5f * acc.w + __ldg(&bias[c + 3]);
            *(float4*)&g_out2[(size_t)n * 64 + c] = o;
        }
    }
}

// ---------------- layer 2 GEMM + fused attention scores ----------------
// g_h(fp16) = g_out1 @ W2 ([NPAD,128]@[128,128]); es/ed computed in fp32 from
// register-resident result.
__global__ void k_gemm2(const float* __restrict__ W2,
                        const float* __restrict__ as, const float* __restrict__ ad) {
    __shared__ float sIn[64 * 128];  // 32KB
    __shared__ float sW[16 * 128];   // 8KB
    int tid = threadIdx.x;           // 256 threads
    int nbase = blockIdx.x * 64;

#pragma unroll
    for (int r = 0; r < 8; r++) {
        int idx = tid + r * 256;
        ((float4*)sIn)[idx] = ((const float4*)(g_out1 + (size_t)nbase * 128))[idx];
    }

    float acc[8][4];
#pragma unroll
    for (int m = 0; m < 8; m++) { acc[m][0] = acc[m][1] = acc[m][2] = acc[m][3] = 0.f; }
    int jq = tid & 31;   // column quad
    int mg = tid >> 5;   // node group (one warp per mg)
    __syncthreads();

    for (int kt = 0; kt < 8; kt++) {
#pragma unroll
        for (int r = 0; r < 2; r++) {
            int idx = tid + r * 256;
            ((float4*)sW)[idx] = ((const float4*)(W2 + kt * 16 * 128))[idx];
        }
        __syncthreads();
#pragma unroll
        for (int k = 0; k < 16; k++) {
            float4 w = *(float4*)&sW[k * 128 + jq * 4];
#pragma unroll
            for (int m = 0; m < 8; m++) {
                float v = sIn[(mg * 8 + m) * 128 + kt * 16 + k];
                acc[m][0] += v * w.x; acc[m][1] += v * w.y;
                acc[m][2] += v * w.z; acc[m][3] += v * w.w;
            }
        }
        __syncthreads();
    }

    // store h as fp16
#pragma unroll
    for (int m = 0; m < 8; m++) {
        int nn = nbase + mg * 8 + m;
        __half2 h01 = __floats2half2_rn(acc[m][0], acc[m][1]);
        __half2 h23 = __floats2half2_rn(acc[m][2], acc[m][3]);
        uint2 u;
        u.x = *(unsigned*)&h01; u.y = *(unsigned*)&h23;
        ((uint2*)(g_h + (size_t)nn * 128))[jq] = u;
    }

    // fused attention scores (fp32)
    float4 av = *(const float4*)(as + jq * 4);
    float4 dv = *(const float4*)(ad + jq * 4);
    float ps[8], pd[8];
#pragma unroll
    for (int m = 0; m < 8; m++) {
        ps[m] = acc[m][0] * av.x + acc[m][1] * av.y + acc[m][2] * av.z + acc[m][3] * av.w;
        pd[m] = acc[m][0] * dv.x + acc[m][1] * dv.y + acc[m][2] * dv.z + acc[m][3] * dv.w;
    }
#pragma unroll
    for (int off = 8; off; off >>= 1) {
#pragma unroll
        for (int m = 0; m < 8; m++) {
            ps[m] += __shfl_xor_sync(0xffffffffu, ps[m], off);
            pd[m] += __shfl_xor_sync(0xffffffffu, pd[m], off);
        }
    }
    if (jq == 0 || jq == 16) {
        int h = jq >> 4;
#pragma unroll
        for (int m = 0; m < 8; m++) {
            int nn = nbase + mg * 8 + m;
            if (nn < NN) {
                g_es[2 * nn + h] = ps[m];
                g_ed[2 * nn + h] = pd[m];
            }
        }
    }
}

// ---------------- classifier: relu(out2@Wc1+bc1)@Wc2+bc2 -> d_out ----------------
__global__ void k_classifier(const float* __restrict__ Wc1, const float* __restrict__ bc1,
                             const float* __restrict__ Wc2, const float* __restrict__ bc2,
                             float* __restrict__ out) {
    __shared__ float sW1[64 * 64];
    __shared__ float sW2[64 * 4];
    __shared__ float sb1[64];
    __shared__ float sb2[4];
    __shared__ float sv[16 * 64];
    __shared__ float sh2[16 * 64];
    int tid = threadIdx.x;          // 256
    int nbase = blockIdx.x * 16;

#pragma unroll
    for (int r = 0; r < 4; r++)
        ((float4*)sW1)[tid + r * 256] = ((const float4*)Wc1)[tid + r * 256];
    if (tid < 64) {
        ((float4*)sW2)[tid] = ((const float4*)Wc2)[tid];
        sb1[tid] = bc1[tid];
    }
    if (tid < 4) sb2[tid] = bc2[tid];
    ((float4*)sv)[tid] = ((const float4*)(g_out2 + (size_t)nbase * 64))[tid];
    __syncthreads();

    {
        int node = tid >> 4;
        int cq = tid & 15;
        float a0 = sb1[cq * 4], a1 = sb1[cq * 4 + 1], a2 = sb1[cq * 4 + 2], a3 = sb1[cq * 4 + 3];
#pragma unroll
        for (int k = 0; k < 64; k++) {
            float v = sv[node * 64 + k];
            float4 w = *(float4*)&sW1[k * 64 + cq * 4];
            a0 += v * w.x; a1 += v * w.y; a2 += v * w.z; a3 += v * w.w;
        }
        *(float4*)&sh2[node * 64 + cq * 4] =
            make_float4(fmaxf(a0, 0.f), fmaxf(a1, 0.f), fmaxf(a2, 0.f), fmaxf(a3, 0.f));
    }
    __syncthreads();

    if (tid < 64) {
        int n2 = tid >> 2, o = tid & 3;
        float a = sb2[o];
#pragma unroll
        for (int k = 0; k < 64; k++) a += sh2[n2 * 64 + k] * sW2[k * 4 + o];
        out[(size_t)(nbase + n2) * 4 + o] = a;
    }
}

// ---------------- launch ----------------
extern "C" void kernel_launch(void* const* d_in, const int* in_sizes, int n_in,
                              void* d_out, int out_size) {
    const float* x   = (const float*)d_in[0];
    const int*   ei  = (const int*)d_in[1];
    const float* W1  = (const float*)d_in[2];
    const float* as1 = (const float*)d_in[3];
    const float* ad1 = (const float*)d_in[4];
    const float* b1  = (const float*)d_in[5];
    const float* W2  = (const float*)d_in[6];
    const float* as2 = (const float*)d_in[7];
    const float* ad2 = (const float*)d_in[8];
    const float* b2  = (const float*)d_in[9];
    const float* Wc1 = (const float*)d_in[10];
    const float* bc1 = (const float*)d_in[11];
    const float* Wc2 = (const float*)d_in[12];
    const float* bc2 = (const float*)d_in[13];
    float* out = (float*)d_out;

    // CSR build (dst-major, includes self-loops)
    k_init_deg<<<(NN + 255) / 256, 256>>>();
    k_count<<<(NE + 255) / 256, 256>>>(ei);
    k_part<<<SCAN_BLKS, 256>>>();
    k_scanpart<<<1, 128>>>();
    k_scanfinal<<<SCAN_BLKS, 256>>>();
    k_scatter<<<(ET + 255) / 256, 256>>>(ei);

    // layer 1
    k_transform1<<<NN, 128>>>(x, W1, as1, ad1);
    k_agg<1><<<(NN + 7) / 8, 256>>>(b1);

    // layer 2 (GEMM with fused attention scores)
    k_gemm2<<<NPAD / 64, 256>>>(W2, as2, ad2);
    k_agg<2><<<(NN + 7) / 8, 256>>>(b2);

    // classifier
    k_classifier<<<NN / 16, 256>>>(Wc1, bc1, Wc2, bc2, out);
}

// round 4
// speedup vs baseline: 1.5128x; 1.0814x over previous
#include <cuda_runtime.h>
#include <cuda_fp16.h>

#define NN   100000
#define NE   1600000
#define ET   (NE + NN)
#define NPAD 100096   // multiple of 64 for guard-free GEMM tiles
#define SCAN_BLKS ((NN + 1023) / 1024)   // 98

// ---------------- scratch (device globals; no allocations) ----------------
__device__ int    g_deg[NN];          // invariant: all-zero at kernel_launch entry
__device__ int    g_rowptr[NN + 1];
__device__ int    g_cursor[NN];
__device__ int    g_srcs[ET];
__device__ int    g_part[SCAN_BLKS];
__device__ int    g_partscan[SCAN_BLKS];
__device__ __half g_h[NPAD * 128];    // transformed features, fp16 (reused both layers)
__device__ float  g_es[NN * 2];
__device__ float  g_ed[NN * 2];
__device__ __half g_out1[NPAD * 128]; // layer-1 output (relu'd, concat heads), fp16
__device__ float  g_out2[NN * 64];    // layer-2 output (head mean), fp32

// ---------------- CSR build ----------------
__global__ void k_count(const int* __restrict__ ei) {
    int i = blockIdx.x * blockDim.x + threadIdx.x;
    if (i < NE) atomicAdd(&g_deg[ei[NE + i]], 1);  // dst = ei[1][i]
}

__global__ void k_part() {  // partial sums of (deg+1) per 1024-elem block
    __shared__ int sh[256];
    int base = blockIdx.x * 1024;
    int t = threadIdx.x;
    int idx = base + t * 4;
    int s = 0;
#pragma unroll
    for (int r = 0; r < 4; r++) s += (idx + r < NN) ? (g_deg[idx + r] + 1) : 0;
    sh[t] = s;
    __syncthreads();
    for (int off = 128; off; off >>= 1) {
        if (t < off) sh[t] += sh[t + off];
        __syncthreads();
    }
    if (t == 0) g_part[blockIdx.x] = sh[0];
}

__global__ void k_scanpart() {  // 1 block: exclusive scan of 98 partials
    __shared__ int sh[128];
    int t = threadIdx.x;
    int v = (t < SCAN_BLKS) ? g_part[t] : 0;
    sh[t] = v;
    __syncthreads();
    for (int off = 1; off < 128; off <<= 1) {
        int tv = (t >= off) ? sh[t - off] : 0;
        __syncthreads();
        sh[t] += tv;
        __syncthreads();
    }
    if (t < SCAN_BLKS) g_partscan[t] = sh[t] - v;
    if (t == 0) g_rowptr[NN] = ET;
}

__global__ void k_scanfinal() {  // 98 blocks × 256 threads; also zeroes g_deg for next call
    __shared__ int sh[256];
    int base = blockIdx.x * 1024;
    int t = threadIdx.x;
    int idx = base + t * 4;
    int v[4];
    int s = 0;
#pragma unroll
    for (int r = 0; r < 4; r++) {
        v[r] = (idx + r < NN) ? (g_deg[idx + r] + 1) : 0;
        if (idx + r < NN) g_deg[idx + r] = 0;   // restore invariant
        s += v[r];
    }
    sh[t] = s;
    __syncthreads();
    for (int off = 1; off < 256; off <<= 1) {
        int tv = (t >= off) ? sh[t - off] : 0;
        __syncthreads();
        sh[t] += tv;
        __syncthreads();
    }
    int excl = sh[t] - s + g_partscan[blockIdx.x];
#pragma unroll
    for (int r = 0; r < 4; r++) {
        if (idx + r < NN) {
            g_rowptr[idx + r] = excl;
            g_cursor[idx + r] = excl;
            excl += v[r];
        }
    }
}

__global__ void k_scatter(const int* __restrict__ ei) {
    int i = blockIdx.x * blockDim.x + threadIdx.x;
    if (i < NE) {
        int s = ei[i], d = ei[NE + i];
        int pos = atomicAdd(&g_cursor[d], 1);
        g_srcs[pos] = s;
    } else if (i < ET) {
        int n = i - NE;
        int pos = atomicAdd(&g_cursor[n], 1);
        g_srcs[pos] = n;
    }
}

// ---------------- layer 1 transform + attention scores ----------------
// 6250 blocks × 256 threads; each block handles 16 nodes (2 in parallel × 8 iters).
// W1 column + attention vector entries held in registers, reused 16×.
__global__ void k_transform1(const float* __restrict__ x, const float* __restrict__ W1,
                             const float* __restrict__ as, const float* __restrict__ ad) {
    __shared__ float sx[16 * 7];
    __shared__ float red[8][2];
    int tid = threadIdx.x;
    int nb = blockIdx.x * 16;
    int ch = tid & 127;
    int hf = tid >> 7;   // 0 or 1: which of the 2 parallel nodes
    float w1r[7];
#pragma unroll
    for (int k = 0; k < 7; k++) w1r[k] = __ldg(&W1[k * 128 + ch]);
    float asr = __ldg(&as[ch]), adr = __ldg(&ad[ch]);
    if (tid < 112) sx[tid] = x[nb * 7 + tid];
    __syncthreads();

#pragma unroll
    for (int i = 0; i < 8; i++) {
        int j = i * 2 + hf;      // node within block
        int n = nb + j;
        float acc = 0.f;
#pragma unroll
        for (int k = 0; k < 7; k++) acc += sx[j * 7 + k] * w1r[k];
        g_h[(size_t)n * 128 + ch] = __float2half(acc);

        float ps = acc * asr, pd = acc * adr;
#pragma unroll
        for (int off = 16; off; off >>= 1) {
            ps += __shfl_xor_sync(0xffffffffu, ps, off);
            pd += __shfl_xor_sync(0xffffffffu, pd, off);
        }
        int w = tid >> 5;
        if ((tid & 31) == 0) { red[w][0] = ps; red[w][1] = pd; }
        __syncthreads();
        if (tid == hf * 128) {   // thread 0 → node A, thread 128 → node B
            int rb = hf * 4;
            float2 esv = make_float2(red[rb][0] + red[rb + 1][0], red[rb + 2][0] + red[rb + 3][0]);
            float2 edv = make_float2(red[rb][1] + red[rb + 1][1], red[rb + 2][1] + red[rb + 3][1]);
            *(float2*)(g_es + 2 * n) = esv;
            *(float2*)(g_ed + 2 * n) = edv;
        }
        __syncthreads();
    }
}

// ---------------- segment-softmax + aggregation ----------------
// 3125 blocks × 256 threads; each warp handles 4 nodes sequentially.
// Single pass, no max subtraction (scores bounded: |e| < ~10 by construction).
template <int LAYER>
__global__ void k_agg(const float* __restrict__ bias) {
    int gw = (blockIdx.x * blockDim.x + threadIdx.x) >> 5;
    int lane = threadIdx.x & 31;
    int head = lane >> 4;
    float4 bv = make_float4(0.f, 0.f, 0.f, 0.f);
    if (LAYER == 1)      bv = *(const float4*)(bias + lane * 4);
    else if (lane < 16)  bv = *(const float4*)(bias + lane * 4);

    for (int q = 0; q < 4; q++) {
        int n = gw * 4 + q;
        int beg = g_rowptr[n], end = g_rowptr[n + 1];
        float ed0 = g_ed[2 * n], ed1 = g_ed[2 * n + 1];

        float sw0 = 0.f, sw1 = 0.f;
        float4 acc = make_float4(0.f, 0.f, 0.f, 0.f);

        for (int base = beg; base < end; base += 32) {
            int j = base + lane;
            int src_c = 0;
            float w0_c = 0.f, w1_c = 0.f;
            if (j < end) {
                src_c = g_srcs[j];
                float2 es = *(const float2*)(g_es + 2 * src_c);
                float e0 = es.x + ed0; e0 = e0 > 0.f ? e0 : 0.2f * e0;
                float e1 = es.y + ed1; e1 = e1 > 0.f ? e1 : 0.2f * e1;
                w0_c = __expf(e0);
                w1_c = __expf(e1);
            }
            sw0 += w0_c; sw1 += w1_c;

            int cnt = end - base; if (cnt > 32) cnt = 32;
            for (int jj = 0; jj < cnt; jj++) {
                int   src = __shfl_sync(0xffffffffu, src_c, jj);
                float w0  = __shfl_sync(0xffffffffu, w0_c, jj);
                float w1  = __shfl_sync(0xffffffffu, w1_c, jj);
                float w   = head ? w1 : w0;
                uint2 u = ((const uint2*)(g_h + (size_t)src * 128))[lane];
                float2 f01 = __half22float2(*(__half2*)&u.x);
                float2 f23 = __half22float2(*(__half2*)&u.y);
                acc.x += w * f01.x; acc.y += w * f01.y;
                acc.z += w * f23.x; acc.w += w * f23.y;
            }
        }

#pragma unroll
        for (int off = 16; off; off >>= 1) {
            sw0 += __shfl_xor_sync(0xffffffffu, sw0, off);
            sw1 += __shfl_xor_sync(0xffffffffu, sw1, off);
        }
        float invs = 1.f / (head ? sw1 : sw0);

        if (LAYER == 1) {
            float4 o;
            o.x = fmaxf(acc.x * invs + bv.x, 0.f);
            o.y = fmaxf(acc.y * invs + bv.y, 0.f);
            o.z = fmaxf(acc.z * invs + bv.z, 0.f);
            o.w = fmaxf(acc.w * invs + bv.w, 0.f);
            __half2 h01 = __floats2half2_rn(o.x, o.y);
            __half2 h23 = __floats2half2_rn(o.z, o.w);
            uint2 u;
            u.x = *(unsigned*)&h01; u.y = *(unsigned*)&h23;
            ((uint2*)(g_out1 + (size_t)n * 128))[lane] = u;
        } else {
            acc.x *= invs; acc.y *= invs; acc.z *= invs; acc.w *= invs;
            acc.x += __shfl_xor_sync(0xffffffffu, acc.x, 16);
            acc.y += __shfl_xor_sync(0xffffffffu, acc.y, 16);
            acc.z += __shfl_xor_sync(0xffffffffu, acc.z, 16);
            acc.w += __shfl_xor_sync(0xffffffffu, acc.w, 16);
            if (lane < 16) {
                float4 o;
                o.x = 0.5f * acc.x + bv.x;
                o.y = 0.5f * acc.y + bv.y;
                o.z = 0.5f * acc.z + bv.z;
                o.w = 0.5f * acc.w + bv.w;
                *(float4*)&g_out2[(size_t)n * 64 + lane * 4] = o;
            }
        }
    }
}

// ---------------- layer 2 GEMM + fused attention scores ----------------
// g_h(fp16) = g_out1(fp16) @ W2 ([NPAD,128]@[128,128]); fp32 math in smem/regs.
__global__ void k_gemm2(const float* __restrict__ W2,
                        const float* __restrict__ as, const float* __restrict__ ad) {
    __shared__ float sIn[64 * 128];  // 32KB
    __shared__ float sW[16 * 128];   // 8KB
    int tid = threadIdx.x;           // 256 threads
    int nbase = blockIdx.x * 64;

#pragma unroll
    for (int r = 0; r < 4; r++) {
        int idx = tid + r * 256;     // uint4-of-8-halves index, 1024 total
        uint4 u = ((const uint4*)(g_out1 + (size_t)nbase * 128))[idx];
        __half2* hp = (__half2*)&u;
        float2 a = __half22float2(hp[0]);
        float2 b = __half22float2(hp[1]);
        float2 c = __half22float2(hp[2]);
        float2 d = __half22float2(hp[3]);
        ((float4*)sIn)[idx * 2]     = make_float4(a.x, a.y, b.x, b.y);
        ((float4*)sIn)[idx * 2 + 1] = make_float4(c.x, c.y, d.x, d.y);
    }

    float acc[8][4];
#pragma unroll
    for (int m = 0; m < 8; m++) { acc[m][0] = acc[m][1] = acc[m][2] = acc[m][3] = 0.f; }
    int jq = tid & 31;   // column quad
    int mg = tid >> 5;   // node group (one warp per mg)
    __syncthreads();

    for (int kt = 0; kt < 8; kt++) {
#pragma unroll
        for (int r = 0; r < 2; r++) {
            int idx = tid + r * 256;
            ((float4*)sW)[idx] = ((const float4*)(W2 + kt * 16 * 128))[idx];
        }
        __syncthreads();
#pragma unroll
        for (int k = 0; k < 16; k++) {
            float4 w = *(float4*)&sW[k * 128 + jq * 4];
#pragma unroll
            for (int m = 0; m < 8; m++) {
                float v = sIn[(mg * 8 + m) * 128 + kt * 16 + k];
                acc[m][0] += v * w.x; acc[m][1] += v * w.y;
                acc[m][2] += v * w.z; acc[m][3] += v * w.w;
            }
        }
        __syncthreads();
    }

    // store h as fp16
#pragma unroll
    for (int m = 0; m < 8; m++) {
        int nn = nbase + mg * 8 + m;
        __half2 h01 = __floats2half2_rn(acc[m][0], acc[m][1]);
        __half2 h23 = __floats2half2_rn(acc[m][2], acc[m][3]);
        uint2 u;
        u.x = *(unsigned*)&h01; u.y = *(unsigned*)&h23;
        ((uint2*)(g_h + (size_t)nn * 128))[jq] = u;
    }

    // fused attention scores (fp32)
    float4 av = *(const float4*)(as + jq * 4);
    float4 dv = *(const float4*)(ad + jq * 4);
    float ps[8], pd[8];
#pragma unroll
    for (int m = 0; m < 8; m++) {
        ps[m] = acc[m][0] * av.x + acc[m][1] * av.y + acc[m][2] * av.z + acc[m][3] * av.w;
        pd[m] = acc[m][0] * dv.x + acc[m][1] * dv.y + acc[m][2] * dv.z + acc[m][3] * dv.w;
    }
#pragma unroll
    for (int off = 8; off; off >>= 1) {
#pragma unroll
        for (int m = 0; m < 8; m++) {
            ps[m] += __shfl_xor_sync(0xffffffffu, ps[m], off);
            pd[m] += __shfl_xor_sync(0xffffffffu, pd[m], off);
        }
    }
    if (jq == 0 || jq == 16) {
        int h = jq >> 4;
#pragma unroll
        for (int m = 0; m < 8; m++) {
            int nn = nbase + mg * 8 + m;
            if (nn < NN) {
                g_es[2 * nn + h] = ps[m];
                g_ed[2 * nn + h] = pd[m];
            }
        }
    }
}

// ---------------- classifier: relu(out2@Wc1+bc1)@Wc2+bc2 -> d_out ----------------
__global__ void k_classifier(const float* __restrict__ Wc1, const float* __restrict__ bc1,
                             const float* __restrict__ Wc2, const float* __restrict__ bc2,
                             float* __restrict__ out) {
    __shared__ float sW1[64 * 64];
    __shared__ float sW2[64 * 4];
    __shared__ float sb1[64];
    __shared__ float sb2[4];
    __shared__ float sv[16 * 64];
    __shared__ float sh2[16 * 64];
    int tid = threadIdx.x;          // 256
    int nbase = blockIdx.x * 16;

#pragma unroll
    for (int r = 0; r < 4; r++)
        ((float4*)sW1)[tid + r * 256] = ((const float4*)Wc1)[tid + r * 256];
    if (tid < 64) {
        ((float4*)sW2)[tid] = ((const float4*)Wc2)[tid];
        sb1[tid] = bc1[tid];
    }
    if (tid < 4) sb2[tid] = bc2[tid];
    ((float4*)sv)[tid] = ((const float4*)(g_out2 + (size_t)nbase * 64))[tid];
    __syncthreads();

    {
        int node = tid >> 4;
        int cq = tid & 15;
        float a0 = sb1[cq * 4], a1 = sb1[cq * 4 + 1], a2 = sb1[cq * 4 + 2], a3 = sb1[cq * 4 + 3];
#pragma unroll
        for (int k = 0; k < 64; k++) {
            float v = sv[node * 64 + k];
            float4 w = *(float4*)&sW1[k * 64 + cq * 4];
            a0 += v * w.x; a1 += v * w.y; a2 += v * w.z; a3 += v * w.w;
        }
        *(float4*)&sh2[node * 64 + cq * 4] =
            make_float4(fmaxf(a0, 0.f), fmaxf(a1, 0.f), fmaxf(a2, 0.f), fmaxf(a3, 0.f));
    }
    __syncthreads();

    if (tid < 64) {
        int n2 = tid >> 2, o = tid & 3;
        float a = sb2[o];
#pragma unroll
        for (int k = 0; k < 64; k++) a += sh2[n2 * 64 + k] * sW2[k * 4 + o];
        out[(size_t)(nbase + n2) * 4 + o] = a;
    }
}

// ---------------- launch ----------------
extern "C" void kernel_launch(void* const* d_in, const int* in_sizes, int n_in,
                              void* d_out, int out_size) {
    const float* x   = (const float*)d_in[0];
    const int*   ei  = (const int*)d_in[1];
    const float* W1  = (const float*)d_in[2];
    const float* as1 = (const float*)d_in[3];
    const float* ad1 = (const float*)d_in[4];
    const float* b1  = (const float*)d_in[5];
    const float* W2  = (const float*)d_in[6];
    const float* as2 = (const float*)d_in[7];
    const float* ad2 = (const float*)d_in[8];
    const float* b2  = (const float*)d_in[9];
    const float* Wc1 = (const float*)d_in[10];
    const float* bc1 = (const float*)d_in[11];
    const float* Wc2 = (const float*)d_in[12];
    const float* bc2 = (const float*)d_in[13];
    float* out = (float*)d_out;

    // CSR build (g_deg is all-zero at entry; k_scanfinal re-zeroes it)
    k_count<<<(NE + 255) / 256, 256>>>(ei);                       // 1
    k_part<<<SCAN_BLKS, 256>>>();                                 // 2
    k_scanpart<<<1, 128>>>();                                     // 3
    k_transform1<<<NN / 16, 256>>>(x, W1, as1, ad1);              // 4 (profiled slot)
    k_scanfinal<<<SCAN_BLKS, 256>>>();                            // 5
    k_scatter<<<(ET + 255) / 256, 256>>>(ei);                     // 6

    // layer 1
    k_agg<1><<<NN / 32, 256>>>(b1);                               // 7

    // layer 2 (GEMM with fused attention scores)
    k_gemm2<<<NPAD / 64, 256>>>(W2, as2, ad2);                    // 8
    k_agg<2><<<NN / 32, 256>>>(b2);                               // 9

    // classifier
    k_classifier<<<NN / 16, 256>>>(Wc1, bc1, Wc2, bc2, out);      // 10
}

// round 5
// speedup vs baseline: 1.6230x; 1.0728x over previous
#include <cuda_runtime.h>
#include <cuda_fp16.h>

#define NN   100000
#define NE   1600000
#define ET   (NE + NN)
#define NPAD 100096   // multiple of 64 for guard-free GEMM tiles
#define SCAN_BLKS ((NN + 1023) / 1024)   // 98
#define CNT_BLKS  (NE / 256)             // 6250 exactly
#define TR_BLKS   (NN / 16)              // 6250
#define SC_BLKS   ((ET + 255) / 256)     // 6641

// ---------------- scratch (device globals; no allocations) ----------------
__device__ int    g_deg[NN];          // invariant: all-zero at kernel_launch entry
__device__ int    g_rowptr[NN + 1];
__device__ int    g_cursor[NN];
__device__ int    g_srcs[ET];
__device__ int    g_aggv[SCAN_BLKS];
__device__ int    g_prefv[SCAN_BLKS];
__device__ int    g_status[SCAN_BLKS];
__device__ float  g_va[7 * 4];        // per-k dot of W1 col-block with a_src/a_dst
__device__ __half g_W2aT[128 * 128];  // fp16 hi part of W2, transposed [N][K]
__device__ __half g_W2bT[128 * 128];  // fp16 residual part, transposed [N][K]
__device__ __half g_h[NPAD * 128];    // transformed features, fp16
__device__ float  g_es[NN * 2];
__device__ float  g_ed[NN * 2];
__device__ __half g_out1[NPAD * 128]; // layer-1 output (relu'd), fp16
__device__ float  g_out2[NN * 64];    // layer-2 output (head mean), fp32

// ---------------- kernel 1: edge count + prep (W2 split/transpose, va, flags) ----------------
__global__ void k_count_prep(const int* __restrict__ ei,
                             const float* __restrict__ W1,
                             const float* __restrict__ as1, const float* __restrict__ ad1,
                             const float* __restrict__ W2) {
    int b = blockIdx.x;
    int t = threadIdx.x;
    if (b < CNT_BLKS) {
        int i = b * 256 + t;
        atomicAdd(&g_deg[ei[NE + i]], 1);  // dst = ei[1][i]
    } else if (b == CNT_BLKS) {
        // W2 -> fp16 hi + fp16 residual, transposed to [N][K]
        for (int idx = t; idx < 128 * 128; idx += 256) {
            int k = idx >> 7, n = idx & 127;
            float w = W2[idx];
            __half a = __float2half_rn(w);
            __half bb = __float2half_rn(w - __half2float(a));
            g_W2aT[n * 128 + k] = a;
            g_W2bT[n * 128 + k] = bb;
        }
    } else {
        // va[k][comp]: comp = {es_h0, es_h1, ed_h0, ed_h1}
        if (t < 28) {
            int k = t >> 2, comp = t & 3;
            int h = comp & 1;
            const float* vec = (comp < 2) ? as1 : ad1;
            float s = 0.f;
#pragma unroll
            for (int c = 0; c < 64; c++) s += W1[k * 128 + h * 64 + c] * vec[h * 64 + c];
            g_va[k * 4 + comp] = s;
        }
        if (t >= 32 && t < 32 + SCAN_BLKS) g_status[t - 32] = 0;  // reset lookback flags
    }
}

// ---------------- kernel 2: single-pass scan (decoupled lookback) ----------------
__global__ void k_scanall() {  // SCAN_BLKS blocks x 256 threads; 4 nodes/thread
    __shared__ int sh[256];
    __shared__ int s_prefix;
    int b = blockIdx.x;
    int t = threadIdx.x;
    int base = b * 1024;
    int idx = base + t * 4;
    int v[4];
    int s = 0;
#pragma unroll
    for (int r = 0; r < 4; r++) {
        v[r] = (idx + r < NN) ? (g_deg[idx + r] + 1) : 0;  // +1 self-loop
        if (idx + r < NN) g_deg[idx + r] = 0;              // restore invariant
        s += v[r];
    }
    sh[t] = s;
    __syncthreads();
    for (int off = 1; off < 256; off <<= 1) {
        int tv = (t >= off) ? sh[t - off] : 0;
        __syncthreads();
        sh[t] += tv;
        __syncthreads();
    }
    int total = sh[255];
    if (t == 0) {
        if (b == 0) {
            g_prefv[0] = total;
            __threadfence();
            ((volatile int*)g_status)[0] = 2;
            s_prefix = 0;
        } else {
            g_aggv[b] = total;
            __threadfence();
            ((volatile int*)g_status)[b] = 1;
            int run = 0;
            int i = b - 1;
            while (true) {
                int st;
                do { st = ((volatile int*)g_status)[i]; } while (st == 0);
                __threadfence();
                if (st == 1) { run += ((volatile int*)g_aggv)[i]; i--; }
                else         { run += ((volatile int*)g_prefv)[i]; break; }
            }
            g_prefv[b] = run + total;
            __threadfence();
            ((volatile int*)g_status)[b] = 2;
            s_prefix = run;
        }
    }
    __syncthreads();
    int excl = s_prefix + sh[t] - s;
#pragma unroll
    for (int r = 0; r < 4; r++) {
        if (idx + r < NN) {
            g_rowptr[idx + r] = excl;
            g_cursor[idx + r] = excl;
            excl += v[r];
            if (idx + r == NN - 1) g_rowptr[NN] = excl;
        }
    }
}

// ---------------- kernel 3: fused scatter + layer-1 transform ----------------
// blocks [0, TR_BLKS): transform (16 nodes each, no warp reductions — es/ed via g_va)
// blocks [TR_BLKS, TR_BLKS+SC_BLKS): CSR scatter
__global__ void k_scatter_transform(const int* __restrict__ ei,
                                    const float* __restrict__ x,
                                    const float* __restrict__ W1) {
    int b = blockIdx.x;
    int t = threadIdx.x;
    if (b < TR_BLKS) {
        __shared__ float sx[16 * 7];
        int nb = b * 16;
        int ch = t & 127;
        int hf = t >> 7;
        float w1r[7];
#pragma unroll
        for (int k = 0; k < 7; k++) w1r[k] = __ldg(&W1[k * 128 + ch]);
        if (t < 112) sx[t] = x[nb * 7 + t];
        __syncthreads();
#pragma unroll
        for (int i = 0; i < 8; i++) {
            int j = hf * 8 + i;
            float acc = 0.f;
#pragma unroll
            for (int k = 0; k < 7; k++) acc += sx[j * 7 + k] * w1r[k];
            g_h[(size_t)(nb + j) * 128 + ch] = __float2half(acc);
        }
        // es/ed: 64 threads, 4 components x 16 nodes, 7-FMA dots with g_va
        if (t < 64) {
            int j = t >> 2, comp = t & 3;
            int n = nb + j;
            float val = 0.f;
#pragma unroll
            for (int k = 0; k < 7; k++) val += sx[j * 7 + k] * g_va[k * 4 + comp];
            if (comp < 2) g_es[2 * n + comp] = val;
            else          g_ed[2 * n + comp - 2] = val;
        }
    } else {
        int i = (b - TR_BLKS) * 256 + t;
        if (i < NE) {
            int s = ei[i], d = ei[NE + i];
            int pos = atomicAdd(&g_cursor[d], 1);
            g_srcs[pos] = s;
        } else if (i < ET) {
            int n = i - NE;
            int pos = atomicAdd(&g_cursor[n], 1);
            g_srcs[pos] = n;
        }
    }
}

// ---------------- segment-softmax + aggregation ----------------
template <int LAYER>
__global__ void k_agg(const float* __restrict__ bias) {
    int gw = (blockIdx.x * blockDim.x + threadIdx.x) >> 5;
    int lane = threadIdx.x & 31;
    int head = lane >> 4;
    float4 bv = make_float4(0.f, 0.f, 0.f, 0.f);
    if (LAYER == 1)      bv = *(const float4*)(bias + lane * 4);
    else if (lane < 16)  bv = *(const float4*)(bias + lane * 4);

    for (int q = 0; q < 4; q++) {
        int n = gw * 4 + q;
        int beg = g_rowptr[n], end = g_rowptr[n + 1];
        float ed0 = g_ed[2 * n], ed1 = g_ed[2 * n + 1];

        float sw0 = 0.f, sw1 = 0.f;
        float4 acc = make_float4(0.f, 0.f, 0.f, 0.f);

        for (int base = beg; base < end; base += 32) {
            int j = base + lane;
            int src_c = 0;
            float w0_c = 0.f, w1_c = 0.f;
            if (j < end) {
                src_c = g_srcs[j];
                float2 es = *(const float2*)(g_es + 2 * src_c);
                float e0 = es.x + ed0; e0 = e0 > 0.f ? e0 : 0.2f * e0;
                float e1 = es.y + ed1; e1 = e1 > 0.f ? e1 : 0.2f * e1;
                w0_c = __expf(e0);
                w1_c = __expf(e1);
            }
            sw0 += w0_c; sw1 += w1_c;

            int cnt = end - base; if (cnt > 32) cnt = 32;
            for (int jj = 0; jj < cnt; jj++) {
                int   src = __shfl_sync(0xffffffffu, src_c, jj);
                float w0  = __shfl_sync(0xffffffffu, w0_c, jj);
                float w1  = __shfl_sync(0xffffffffu, w1_c, jj);
                float w   = head ? w1 : w0;
                uint2 u = ((const uint2*)(g_h + (size_t)src * 128))[lane];
                float2 f01 = __half22float2(*(__half2*)&u.x);
                float2 f23 = __half22float2(*(__half2*)&u.y);
                acc.x += w * f01.x; acc.y += w * f01.y;
                acc.z += w * f23.x; acc.w += w * f23.y;
            }
        }

#pragma unroll
        for (int off = 16; off; off >>= 1) {
            sw0 += __shfl_xor_sync(0xffffffffu, sw0, off);
            sw1 += __shfl_xor_sync(0xffffffffu, sw1, off);
        }
        float invs = 1.f / (head ? sw1 : sw0);

        if (LAYER == 1) {
            float4 o;
            o.x = fmaxf(acc.x * invs + bv.x, 0.f);
            o.y = fmaxf(acc.y * invs + bv.y, 0.f);
            o.z = fmaxf(acc.z * invs + bv.z, 0.f);
            o.w = fmaxf(acc.w * invs + bv.w, 0.f);
            __half2 h01 = __floats2half2_rn(o.x, o.y);
            __half2 h23 = __floats2half2_rn(o.z, o.w);
            uint2 u;
            u.x = *(unsigned*)&h01; u.y = *(unsigned*)&h23;
            ((uint2*)(g_out1 + (size_t)n * 128))[lane] = u;
        } else {
            acc.x *= invs; acc.y *= invs; acc.z *= invs; acc.w *= invs;
            acc.x += __shfl_xor_sync(0xffffffffu, acc.x, 16);
            acc.y += __shfl_xor_sync(0xffffffffu, acc.y, 16);
            acc.z += __shfl_xor_sync(0xffffffffu, acc.z, 16);
            acc.w += __shfl_xor_sync(0xffffffffu, acc.w, 16);
            if (lane < 16) {
                float4 o;
                o.x = 0.5f * acc.x + bv.x;
                o.y = 0.5f * acc.y + bv.y;
                o.z = 0.5f * acc.z + bv.z;
                o.w = 0.5f * acc.w + bv.w;
                *(float4*)&g_out2[(size_t)n * 64 + lane * 4] = o;
            }
        }
    }
}

// ---------------- layer 2 GEMM on tensor cores + fused attention scores ----------------
// g_h(fp16) = g_out1(fp16) @ (W2a + W2b)(fp16x2), fp32 accumulate via mma.sync.
// Tile: 64 rows x 128 cols per block; 8 warps = 4(m) x 2(n: head).
__global__ void k_gemm2(const float* __restrict__ as, const float* __restrict__ ad) {
    __shared__ __half sA[64 * 136];    // padded stride 136 (conflict-free frags)
    __shared__ __half sB[128 * 136];   // W2 part, transposed [n][k]
    __shared__ float  sEs[64][2], sEd[64][2];
    int tid = threadIdx.x;             // 256
    int lane = tid & 31;
    int w = tid >> 5;
    int wm = w >> 1;                   // 0..3 (16-row group)
    int wn = w & 1;                    // 0..1 (64-col group = head)
    int nbase = blockIdx.x * 64;

    // load A tile: 64 rows x 128 halves
#pragma unroll
    for (int r = 0; r < 4; r++) {
        int idx = tid + r * 256;       // 1024 uint4 (8 halves each)
        int row = idx >> 4, c8 = idx & 15;
        uint4 u = ((const uint4*)(g_out1 + (size_t)nbase * 128))[idx];
        *(uint4*)&sA[row * 136 + c8 * 8] = u;
    }

    float acc[8][4];
#pragma unroll
    for (int nt = 0; nt < 8; nt++) { acc[nt][0] = acc[nt][1] = acc[nt][2] = acc[nt][3] = 0.f; }

    int r0 = lane >> 2;                // 0..7
    int kq = (lane & 3) * 2;           // 0,2,4,6

    const __half* W2p[2] = {g_W2aT, g_W2bT};
#pragma unroll
    for (int part = 0; part < 2; part++) {
        __syncthreads();
        // load B part: 128 rows(n) x 128 (k)
#pragma unroll
        for (int r = 0; r < 8; r++) {
            int idx = tid + r * 256;   // 2048 uint4
            int row = idx >> 4, c8 = idx & 15;
            uint4 u = ((const uint4*)W2p[part])[idx];
            *(uint4*)&sB[row * 136 + c8 * 8] = u;
        }
        __syncthreads();
#pragma unroll
        for (int ks = 0; ks < 8; ks++) {
            int k0 = ks * 16 + kq;
            int arow = wm * 16 + r0;
            unsigned a0 = *(const unsigned*)&sA[arow * 136 + k0];
            unsigned a1 = *(const unsigned*)&sA[(arow + 8) * 136 + k0];
            unsigned a2 = *(const unsigned*)&sA[arow * 136 + k0 + 8];
            unsigned a3 = *(const unsigned*)&sA[(arow + 8) * 136 + k0 + 8];
#pragma unroll
            for (int nt = 0; nt < 8; nt++) {
                int col = wn * 64 + nt * 8 + r0;
                unsigned b0 = *(const unsigned*)&sB[col * 136 + k0];
                unsigned b1 = *(const unsigned*)&sB[col * 136 + k0 + 8];
                asm volatile(
                    "mma.sync.aligned.m16n8k16.row.col.f32.f16.f16.f32 "
                    "{%0,%1,%2,%3}, {%4,%5,%6,%7}, {%8,%9}, {%0,%1,%2,%3};"
                    : "+f"(acc[nt][0]), "+f"(acc[nt][1]), "+f"(acc[nt][2]), "+f"(acc[nt][3])
                    : "r"(a0), "r"(a1), "r"(a2), "r"(a3), "r"(b0), "r"(b1));
            }
        }
    }

    // epilogue: store h (fp16) + per-row attention-score partials
    int row = wm * 16 + r0;
    float ps0 = 0.f, ps1 = 0.f, pd0 = 0.f, pd1 = 0.f;
#pragma unroll
    for (int nt = 0; nt < 8; nt++) {
        int colb = wn * 64 + nt * 8 + kq;
        __half2 hlo = __floats2half2_rn(acc[nt][0], acc[nt][1]);
        __half2 hhi = __floats2half2_rn(acc[nt][2], acc[nt][3]);
        *(__half2*)&g_h[(size_t)(nbase + row) * 128 + colb] = hlo;
        *(__half2*)&g_h[(size_t)(nbase + row + 8) * 128 + colb] = hhi;
        float a0v = __ldg(&as[colb]), a1v = __ldg(&as[colb + 1]);
        float d0v = __ldg(&ad[colb]), d1v = __ldg(&ad[colb + 1]);
        ps0 += acc[nt][0] * a0v + acc[nt][1] * a1v;
        ps1 += acc[nt][2] * a0v + acc[nt][3] * a1v;
        pd0 += acc[nt][0] * d0v + acc[nt][1] * d1v;
        pd1 += acc[nt][2] * d0v + acc[nt][3] * d1v;
    }
#pragma unroll
    for (int off = 1; off <= 2; off <<= 1) {
        ps0 += __shfl_xor_sync(0xffffffffu, ps0, off);
        ps1 += __shfl_xor_sync(0xffffffffu, ps1, off);
        pd0 += __shfl_xor_sync(0xffffffffu, pd0, off);
        pd1 += __shfl_xor_sync(0xffffffffu, pd1, off);
    }
    if ((lane & 3) == 0) {
        sEs[row][wn] = ps0; sEs[row + 8][wn] = ps1;
        sEd[row][wn] = pd0; sEd[row + 8][wn] = pd1;
    }
    __syncthreads();
    if (tid < 64) {
        int n = nbase + tid;
        if (n < NN) {
            *(float2*)&g_es[2 * n] = make_float2(sEs[tid][0], sEs[tid][1]);
            *(float2*)&g_ed[2 * n] = make_float2(sEd[tid][0], sEd[tid][1]);
        }
    }
}

// ---------------- classifier: relu(out2@Wc1+bc1)@Wc2+bc2 -> d_out ----------------
__global__ void k_classifier(const float* __restrict__ Wc1, const float* __restrict__ bc1,
                             const float* __restrict__ Wc2, const float* __restrict__ bc2,
                             float* __restrict__ out) {
    __shared__ float sW1[64 * 64];
    __shared__ float sW2[64 * 4];
    __shared__ float sb1[64];
    __shared__ float sb2[4];
    __shared__ float sv[16 * 64];
    __shared__ float sh2[16 * 64];
    int tid = threadIdx.x;          // 256
    int nbase = blockIdx.x * 16;

#pragma unroll
    for (int r = 0; r < 4; r++)
        ((float4*)sW1)[tid + r * 256] = ((const float4*)Wc1)[tid + r * 256];
    if (tid < 64) {
        ((float4*)sW2)[tid] = ((const float4*)Wc2)[tid];
        sb1[tid] = bc1[tid];
    }
    if (tid < 4) sb2[tid] = bc2[tid];
    ((float4*)sv)[tid] = ((const float4*)(g_out2 + (size_t)nbase * 64))[tid];
    __syncthreads();

    {
        int node = tid >> 4;
        int cq = tid & 15;
        float a0 = sb1[cq * 4], a1 = sb1[cq * 4 + 1], a2 = sb1[cq * 4 + 2], a3 = sb1[cq * 4 + 3];
#pragma unroll
        for (int k = 0; k < 64; k++) {
            float v = sv[node * 64 + k];
            float4 wv = *(float4*)&sW1[k * 64 + cq * 4];
            a0 += v * wv.x; a1 += v * wv.y; a2 += v * wv.z; a3 += v * wv.w;
        }
        *(float4*)&sh2[node * 64 + cq * 4] =
            make_float4(fmaxf(a0, 0.f), fmaxf(a1, 0.f), fmaxf(a2, 0.f), fmaxf(a3, 0.f));
    }
    __syncthreads();

    if (tid < 64) {
        int n2 = tid >> 2, o = tid & 3;
        float a = sb2[o];
#pragma unroll
        for (int k = 0; k < 64; k++) a += sh2[n2 * 64 + k] * sW2[k * 4 + o];
        out[(size_t)(nbase + n2) * 4 + o] = a;
    }
}

// ---------------- launch ----------------
extern "C" void kernel_launch(void* const* d_in, const int* in_sizes, int n_in,
                              void* d_out, int out_size) {
    const float* x   = (const float*)d_in[0];
    const int*   ei  = (const int*)d_in[1];
    const float* W1  = (const float*)d_in[2];
    const float* as1 = (const float*)d_in[3];
    const float* ad1 = (const float*)d_in[4];
    const float* b1  = (const float*)d_in[5];
    const float* W2  = (const float*)d_in[6];
    const float* as2 = (const float*)d_in[7];
    const float* ad2 = (const float*)d_in[8];
    const float* b2  = (const float*)d_in[9];
    const float* Wc1 = (const float*)d_in[10];
    const float* bc1 = (const float*)d_in[11];
    const float* Wc2 = (const float*)d_in[12];
    const float* bc2 = (const float*)d_in[13];
    float* out = (float*)d_out;

    k_count_prep<<<CNT_BLKS + 2, 256>>>(ei, W1, as1, ad1, W2);          // 1
    k_scanall<<<SCAN_BLKS, 256>>>();                                    // 2
    k_scatter_transform<<<TR_BLKS + SC_BLKS, 256>>>(ei, x, W1);         // 3
    k_agg<1><<<NN / 32, 256>>>(b1);                                     // 4 (profiled)
    k_gemm2<<<NPAD / 64, 256>>>(as2, ad2);                              // 5
    k_agg<2><<<NN / 32, 256>>>(b2);                                     // 6
    k_classifier<<<NN / 16, 256>>>(Wc1, bc1, Wc2, bc2, out);            // 7
}

// round 6
// speedup vs baseline: 1.6824x; 1.0366x over previous
#include <cuda_runtime.h>
#include <cuda_fp16.h>

#define NN   100000
#define NE   1600000
#define ET   (NE + NN)
#define NPAD 100096   // multiple of 64 for guard-free GEMM tiles
#define SCAN_BLKS ((NN + 1023) / 1024)   // 98
#define CNT_BLKS  (NE / 256)             // 6250 exactly
#define TR_BLKS   (NN / 16)              // 6250
#define SC_BLKS   ((ET + 255) / 256)     // 6641

// ---------------- scratch (device globals; no allocations) ----------------
__device__ int    g_deg[NN];          // invariant: all-zero at kernel_launch entry
__device__ int    g_rowptr[NN + 1];
__device__ int    g_cursor[NN];
__device__ int    g_srcs[ET];
__device__ int    g_aggv[SCAN_BLKS];
__device__ int    g_prefv[SCAN_BLKS];
__device__ int    g_status[SCAN_BLKS];
__device__ float  g_va[7 * 4];        // per-k dot of W1 col-block with a_src/a_dst
__device__ __half g_W2aT[128 * 128];  // fp16 hi part of W2, transposed [N][K]
__device__ __half g_W2bT[128 * 128];  // fp16 residual part, transposed [N][K]
__device__ __half g_h[NPAD * 128];    // transformed features, fp16
__device__ float  g_es[NN * 2];
__device__ float  g_ed[NN * 2];
__device__ __half g_out1[NPAD * 128]; // layer-1 output (relu'd), fp16
__device__ float  g_out2[NN * 64];    // layer-2 output (head mean), fp32

// ---------------- kernel 1: edge count + prep (W2 split/transpose, va, flags) ----------------
__global__ void k_count_prep(const int* __restrict__ ei,
                             const float* __restrict__ W1,
                             const float* __restrict__ as1, const float* __restrict__ ad1,
                             const float* __restrict__ W2) {
    int b = blockIdx.x;
    int t = threadIdx.x;
    if (b < CNT_BLKS) {
        int i = b * 256 + t;
        atomicAdd(&g_deg[ei[NE + i]], 1);  // dst = ei[1][i]
    } else if (b == CNT_BLKS) {
        // W2 -> fp16 hi + fp16 residual, transposed to [N][K]
        for (int idx = t; idx < 128 * 128; idx += 256) {
            int k = idx >> 7, n = idx & 127;
            float w = W2[idx];
            __half a = __float2half_rn(w);
            __half bb = __float2half_rn(w - __half2float(a));
            g_W2aT[n * 128 + k] = a;
            g_W2bT[n * 128 + k] = bb;
        }
    } else {
        // va[k][comp]: comp = {es_h0, es_h1, ed_h0, ed_h1}
        if (t < 28) {
            int k = t >> 2, comp = t & 3;
            int h = comp & 1;
            const float* vec = (comp < 2) ? as1 : ad1;
            float s = 0.f;
#pragma unroll
            for (int c = 0; c < 64; c++) s += W1[k * 128 + h * 64 + c] * vec[h * 64 + c];
            g_va[k * 4 + comp] = s;
        }
        if (t >= 32 && t < 32 + SCAN_BLKS) g_status[t - 32] = 0;  // reset lookback flags
    }
}

// ---------------- kernel 2: single-pass scan (decoupled lookback) ----------------
__global__ void k_scanall() {  // SCAN_BLKS blocks x 256 threads; 4 nodes/thread
    __shared__ int sh[256];
    __shared__ int s_prefix;
    int b = blockIdx.x;
    int t = threadIdx.x;
    int base = b * 1024;
    int idx = base + t * 4;
    int v[4];
    int s = 0;
#pragma unroll
    for (int r = 0; r < 4; r++) {
        v[r] = (idx + r < NN) ? (g_deg[idx + r] + 1) : 0;  // +1 self-loop
        if (idx + r < NN) g_deg[idx + r] = 0;              // restore invariant
        s += v[r];
    }
    sh[t] = s;
    __syncthreads();
    for (int off = 1; off < 256; off <<= 1) {
        int tv = (t >= off) ? sh[t - off] : 0;
        __syncthreads();
        sh[t] += tv;
        __syncthreads();
    }
    int total = sh[255];
    if (t == 0) {
        if (b == 0) {
            g_prefv[0] = total;
            __threadfence();
            ((volatile int*)g_status)[0] = 2;
            s_prefix = 0;
        } else {
            g_aggv[b] = total;
            __threadfence();
            ((volatile int*)g_status)[b] = 1;
            int run = 0;
            int i = b - 1;
            while (true) {
                int st;
                do { st = ((volatile int*)g_status)[i]; } while (st == 0);
                __threadfence();
                if (st == 1) { run += ((volatile int*)g_aggv)[i]; i--; }
                else         { run += ((volatile int*)g_prefv)[i]; break; }
            }
            g_prefv[b] = run + total;
            __threadfence();
            ((volatile int*)g_status)[b] = 2;
            s_prefix = run;
        }
    }
    __syncthreads();
    int excl = s_prefix + sh[t] - s;
#pragma unroll
    for (int r = 0; r < 4; r++) {
        if (idx + r < NN) {
            g_rowptr[idx + r] = excl;
            g_cursor[idx + r] = excl;
            excl += v[r];
            if (idx + r == NN - 1) g_rowptr[NN] = excl;
        }
    }
}

// ---------------- kernel 3: fused scatter + layer-1 transform ----------------
__global__ void k_scatter_transform(const int* __restrict__ ei,
                                    const float* __restrict__ x,
                                    const float* __restrict__ W1) {
    int b = blockIdx.x;
    int t = threadIdx.x;
    if (b < TR_BLKS) {
        __shared__ float sx[16 * 7];
        int nb = b * 16;
        int ch = t & 127;
        int hf = t >> 7;
        float w1r[7];
#pragma unroll
        for (int k = 0; k < 7; k++) w1r[k] = __ldg(&W1[k * 128 + ch]);
        if (t < 112) sx[t] = x[nb * 7 + t];
        __syncthreads();
#pragma unroll
        for (int i = 0; i < 8; i++) {
            int j = hf * 8 + i;
            float acc = 0.f;
#pragma unroll
            for (int k = 0; k < 7; k++) acc += sx[j * 7 + k] * w1r[k];
            g_h[(size_t)(nb + j) * 128 + ch] = __float2half(acc);
        }
        // es/ed: 64 threads, 4 components x 16 nodes, 7-FMA dots with g_va
        if (t < 64) {
            int j = t >> 2, comp = t & 3;
            int n = nb + j;
            float val = 0.f;
#pragma unroll
            for (int k = 0; k < 7; k++) val += sx[j * 7 + k] * g_va[k * 4 + comp];
            if (comp < 2) g_es[2 * n + comp] = val;
            else          g_ed[2 * n + comp - 2] = val;
        }
    } else {
        int i = (b - TR_BLKS) * 256 + t;
        if (i < NE) {
            int s = ei[i], d = ei[NE + i];
            int pos = atomicAdd(&g_cursor[d], 1);
            g_srcs[pos] = s;
        } else if (i < ET) {
            int n = i - NE;
            int pos = atomicAdd(&g_cursor[n], 1);
            g_srcs[pos] = n;
        }
    }
}

// ---------------- segment-softmax + aggregation ----------------
// Warp per node (4 sequential). Per 32-edge chunk: lane computes (src, w0, w1)
// for its edge, stores as float4 in per-warp smem; inner loop broadcasts via one
// LDS.128 per edge (replaces 3 SHFLs), unrolled x2 for ILP.
template <int LAYER>
__global__ void k_agg(const float* __restrict__ bias) {
    __shared__ float4 sMeta[8][32];
    int wip = threadIdx.x >> 5;
    int gw = (blockIdx.x * blockDim.x + threadIdx.x) >> 5;
    int lane = threadIdx.x & 31;
    int head = lane >> 4;
    float4 bv = make_float4(0.f, 0.f, 0.f, 0.f);
    if (LAYER == 1)      bv = *(const float4*)(bias + lane * 4);
    else if (lane < 16)  bv = *(const float4*)(bias + lane * 4);
    const __half* hlane = g_h + lane * 4;   // lane's 4-channel column base

    for (int q = 0; q < 4; q++) {
        int n = gw * 4 + q;
        int beg = g_rowptr[n], end = g_rowptr[n + 1];
        float2 edv = *(const float2*)(g_ed + 2 * n);

        float sw0 = 0.f, sw1 = 0.f;
        float4 acc = make_float4(0.f, 0.f, 0.f, 0.f);

        for (int base = beg; base < end; base += 32) {
            int j = base + lane;
            float4 meta = make_float4(0.f, 0.f, 0.f, 0.f);
            if (j < end) {
                int src = __ldg(&g_srcs[j]);
                float2 es = *(const float2*)(g_es + 2 * src);
                float e0 = es.x + edv.x; e0 = e0 > 0.f ? e0 : 0.2f * e0;
                float e1 = es.y + edv.y; e1 = e1 > 0.f ? e1 : 0.2f * e1;
                meta = make_float4(__int_as_float(src), __expf(e0), __expf(e1), 0.f);
            }
            sw0 += meta.y; sw1 += meta.z;
            sMeta[wip][lane] = meta;
            __syncwarp();

            int cnt = end - base; if (cnt > 32) cnt = 32;
            int jj = 0;
            for (; jj + 2 <= cnt; jj += 2) {
                float4 mA = sMeta[wip][jj];
                float4 mB = sMeta[wip][jj + 1];
                float wA = head ? mA.z : mA.y;
                float wB = head ? mB.z : mB.y;
                uint2 uA = *(const uint2*)(hlane + (size_t)__float_as_int(mA.x) * 128);
                uint2 uB = *(const uint2*)(hlane + (size_t)__float_as_int(mB.x) * 128);
                float2 a01 = __half22float2(*(__half2*)&uA.x);
                float2 a23 = __half22float2(*(__half2*)&uA.y);
                float2 b01 = __half22float2(*(__half2*)&uB.x);
                float2 b23 = __half22float2(*(__half2*)&uB.y);
                acc.x += wA * a01.x + wB * b01.x;
                acc.y += wA * a01.y + wB * b01.y;
                acc.z += wA * a23.x + wB * b23.x;
                acc.w += wA * a23.y + wB * b23.y;
            }
            if (jj < cnt) {
                float4 mA = sMeta[wip][jj];
                float wA = head ? mA.z : mA.y;
                uint2 uA = *(const uint2*)(hlane + (size_t)__float_as_int(mA.x) * 128);
                float2 a01 = __half22float2(*(__half2*)&uA.x);
                float2 a23 = __half22float2(*(__half2*)&uA.y);
                acc.x += wA * a01.x; acc.y += wA * a01.y;
                acc.z += wA * a23.x; acc.w += wA * a23.y;
            }
            __syncwarp();
        }

#pragma unroll
        for (int off = 16; off; off >>= 1) {
            sw0 += __shfl_xor_sync(0xffffffffu, sw0, off);
            sw1 += __shfl_xor_sync(0xffffffffu, sw1, off);
        }
        float invs = 1.f / (head ? sw1 : sw0);

        if (LAYER == 1) {
            float4 o;
            o.x = fmaxf(acc.x * invs + bv.x, 0.f);
            o.y = fmaxf(acc.y * invs + bv.y, 0.f);
            o.z = fmaxf(acc.z * invs + bv.z, 0.f);
            o.w = fmaxf(acc.w * invs + bv.w, 0.f);
            __half2 h01 = __floats2half2_rn(o.x, o.y);
            __half2 h23 = __floats2half2_rn(o.z, o.w);
            uint2 u;
            u.x = *(unsigned*)&h01; u.y = *(unsigned*)&h23;
            ((uint2*)(g_out1 + (size_t)n * 128))[lane] = u;
        } else {
            acc.x *= invs; acc.y *= invs; acc.z *= invs; acc.w *= invs;
            acc.x += __shfl_xor_sync(0xffffffffu, acc.x, 16);
            acc.y += __shfl_xor_sync(0xffffffffu, acc.y, 16);
            acc.z += __shfl_xor_sync(0xffffffffu, acc.z, 16);
            acc.w += __shfl_xor_sync(0xffffffffu, acc.w, 16);
            if (lane < 16) {
                float4 o;
                o.x = 0.5f * acc.x + bv.x;
                o.y = 0.5f * acc.y + bv.y;
                o.z = 0.5f * acc.z + bv.z;
                o.w = 0.5f * acc.w + bv.w;
                *(float4*)&g_out2[(size_t)n * 64 + lane * 4] = o;
            }
        }
    }
}

// ---------------- layer 2 GEMM on tensor cores + fused attention scores ----------------
__global__ void k_gemm2(const float* __restrict__ as, const float* __restrict__ ad) {
    __shared__ __half sA[64 * 136];
    __shared__ __half sB[128 * 136];
    __shared__ float  sEs[64][2], sEd[64][2];
    int tid = threadIdx.x;             // 256
    int lane = tid & 31;
    int w = tid >> 5;
    int wm = w >> 1;
    int wn = w & 1;
    int nbase = blockIdx.x * 64;

#pragma unroll
    for (int r = 0; r < 4; r++) {
        int idx = tid + r * 256;
        int row = idx >> 4, c8 = idx & 15;
        uint4 u = ((const uint4*)(g_out1 + (size_t)nbase * 128))[idx];
        *(uint4*)&sA[row * 136 + c8 * 8] = u;
    }

    float acc[8][4];
#pragma unroll
    for (int nt = 0; nt < 8; nt++) { acc[nt][0] = acc[nt][1] = acc[nt][2] = acc[nt][3] = 0.f; }

    int r0 = lane >> 2;
    int kq = (lane & 3) * 2;

    const __half* W2p[2] = {g_W2aT, g_W2bT};
#pragma unroll
    for (int part = 0; part < 2; part++) {
        __syncthreads();
#pragma unroll
        for (int r = 0; r < 8; r++) {
            int idx = tid + r * 256;
            int row = idx >> 4, c8 = idx & 15;
            uint4 u = ((const uint4*)W2p[part])[idx];
            *(uint4*)&sB[row * 136 + c8 * 8] = u;
        }
        __syncthreads();
#pragma unroll
        for (int ks = 0; ks < 8; ks++) {
            int k0 = ks * 16 + kq;
            int arow = wm * 16 + r0;
            unsigned a0 = *(const unsigned*)&sA[arow * 136 + k0];
            unsigned a1 = *(const unsigned*)&sA[(arow + 8) * 136 + k0];
            unsigned a2 = *(const unsigned*)&sA[arow * 136 + k0 + 8];
            unsigned a3 = *(const unsigned*)&sA[(arow + 8) * 136 + k0 + 8];
#pragma unroll
            for (int nt = 0; nt < 8; nt++) {
                int col = wn * 64 + nt * 8 + r0;
                unsigned b0 = *(const unsigned*)&sB[col * 136 + k0];
                unsigned b1 = *(const unsigned*)&sB[col * 136 + k0 + 8];
                asm volatile(
                    "mma.sync.aligned.m16n8k16.row.col.f32.f16.f16.f32 "
                    "{%0,%1,%2,%3}, {%4,%5,%6,%7}, {%8,%9}, {%0,%1,%2,%3};"
                    : "+f"(acc[nt][0]), "+f"(acc[nt][1]), "+f"(acc[nt][2]), "+f"(acc[nt][3])
                    : "r"(a0), "r"(a1), "r"(a2), "r"(a3), "r"(b0), "r"(b1));
            }
        }
    }

    int row = wm * 16 + r0;
    float ps0 = 0.f, ps1 = 0.f, pd0 = 0.f, pd1 = 0.f;
#pragma unroll
    for (int nt = 0; nt < 8; nt++) {
        int colb = wn * 64 + nt * 8 + kq;
        __half2 hlo = __floats2half2_rn(acc[nt][0], acc[nt][1]);
        __half2 hhi = __floats2half2_rn(acc[nt][2], acc[nt][3]);
        *(__half2*)&g_h[(size_t)(nbase + row) * 128 + colb] = hlo;
        *(__half2*)&g_h[(size_t)(nbase + row + 8) * 128 + colb] = hhi;
        float a0v = __ldg(&as[colb]), a1v = __ldg(&as[colb + 1]);
        float d0v = __ldg(&ad[colb]), d1v = __ldg(&ad[colb + 1]);
        ps0 += acc[nt][0] * a0v + acc[nt][1] * a1v;
        ps1 += acc[nt][2] * a0v + acc[nt][3] * a1v;
        pd0 += acc[nt][0] * d0v + acc[nt][1] * d1v;
        pd1 += acc[nt][2] * d0v + acc[nt][3] * d1v;
    }
#pragma unroll
    for (int off = 1; off <= 2; off <<= 1) {
        ps0 += __shfl_xor_sync(0xffffffffu, ps0, off);
        ps1 += __shfl_xor_sync(0xffffffffu, ps1, off);
        pd0 += __shfl_xor_sync(0xffffffffu, pd0, off);
        pd1 += __shfl_xor_sync(0xffffffffu, pd1, off);
    }
    if ((lane & 3) == 0) {
        sEs[row][wn] = ps0; sEs[row + 8][wn] = ps1;
        sEd[row][wn] = pd0; sEd[row + 8][wn] = pd1;
    }
    __syncthreads();
    if (tid < 64) {
        int n = nbase + tid;
        if (n < NN) {
            *(float2*)&g_es[2 * n] = make_float2(sEs[tid][0], sEs[tid][1]);
            *(float2*)&g_ed[2 * n] = make_float2(sEd[tid][0], sEd[tid][1]);
        }
    }
}

// ---------------- classifier: relu(out2@Wc1+bc1)@Wc2+bc2 -> d_out ----------------
__global__ void k_classifier(const float* __restrict__ Wc1, const float* __restrict__ bc1,
                             const float* __restrict__ Wc2, const float* __restrict__ bc2,
                             float* __restrict__ out) {
    __shared__ float sW1[64 * 64];
    __shared__ float sW2[64 * 4];
    __shared__ float sb1[64];
    __shared__ float sb2[4];
    __shared__ float sv[16 * 64];
    __shared__ float sh2[16 * 64];
    int tid = threadIdx.x;          // 256
    int nbase = blockIdx.x * 16;

#pragma unroll
    for (int r = 0; r < 4; r++)
        ((float4*)sW1)[tid + r * 256] = ((const float4*)Wc1)[tid + r * 256];
    if (tid < 64) {
        ((float4*)sW2)[tid] = ((const float4*)Wc2)[tid];
        sb1[tid] = bc1[tid];
    }
    if (tid < 4) sb2[tid] = bc2[tid];
    ((float4*)sv)[tid] = ((const float4*)(g_out2 + (size_t)nbase * 64))[tid];
    __syncthreads();

    {
        int node = tid >> 4;
        int cq = tid & 15;
        float a0 = sb1[cq * 4], a1 = sb1[cq * 4 + 1], a2 = sb1[cq * 4 + 2], a3 = sb1[cq * 4 + 3];
#pragma unroll
        for (int k = 0; k < 64; k++) {
            float v = sv[node * 64 + k];
            float4 wv = *(float4*)&sW1[k * 64 + cq * 4];
            a0 += v * wv.x; a1 += v * wv.y; a2 += v * wv.z; a3 += v * wv.w;
        }
        *(float4*)&sh2[node * 64 + cq * 4] =
            make_float4(fmaxf(a0, 0.f), fmaxf(a1, 0.f), fmaxf(a2, 0.f), fmaxf(a3, 0.f));
    }
    __syncthreads();

    if (tid < 64) {
        int n2 = tid >> 2, o = tid & 3;
        float a = sb2[o];
#pragma unroll
        for (int k = 0; k < 64; k++) a += sh2[n2 * 64 + k] * sW2[k * 4 + o];
        out[(size_t)(nbase + n2) * 4 + o] = a;
    }
}

// ---------------- launch ----------------
extern "C" void kernel_launch(void* const* d_in, const int* in_sizes, int n_in,
                              void* d_out, int out_size) {
    const float* x   = (const float*)d_in[0];
    const int*   ei  = (const int*)d_in[1];
    const float* W1  = (const float*)d_in[2];
    const float* as1 = (const float*)d_in[3];
    const float* ad1 = (const float*)d_in[4];
    const float* b1  = (const float*)d_in[5];
    const float* W2  = (const float*)d_in[6];
    const float* as2 = (const float*)d_in[7];
    const float* ad2 = (const float*)d_in[8];
    const float* b2  = (const float*)d_in[9];
    const float* Wc1 = (const float*)d_in[10];
    const float* bc1 = (const float*)d_in[11];
    const float* Wc2 = (const float*)d_in[12];
    const float* bc2 = (const float*)d_in[13];
    float* out = (float*)d_out;

    k_count_prep<<<CNT_BLKS + 2, 256>>>(ei, W1, as1, ad1, W2);          // 1
    k_scanall<<<SCAN_BLKS, 256>>>();                                    // 2
    k_scatter_transform<<<TR_BLKS + SC_BLKS, 256>>>(ei, x, W1);         // 3
    k_agg<1><<<NN / 32, 256>>>(b1);                                     // 4 (profiled)
    k_gemm2<<<NPAD / 64, 256>>>(as2, ad2);                              // 5
    k_agg<2><<<NN / 32, 256>>>(b2);                                     // 6
    k_classifier<<<NN / 16, 256>>>(Wc1, bc1, Wc2, bc2, out);            // 7
}

// round 7
// speedup vs baseline: 1.7544x; 1.0428x over previous
#include <cuda_runtime.h>
#include <cuda_fp16.h>

#define NN   100000
#define NE   1600000
#define ET   (NE + NN)
#define NPAD 100096   // multiple of 64 for guard-free GEMM tiles
#define SCAN_BLKS ((NN + 1023) / 1024)   // 98
#define CNT_BLKS  (NE / 256)             // 6250 exactly
#define TR_BLKS   (NN / 16)              // 6250
#define SC_BLKS   ((ET + 255) / 256)     // 6641

// ---------------- scratch (device globals; no allocations) ----------------
__device__ int    g_deg[NN];          // invariant: all-zero at kernel_launch entry
__device__ int    g_rowptr[NN + 1];
__device__ int    g_cursor[NN];
__device__ int    g_srcs[ET];
__device__ int    g_aggv[SCAN_BLKS];
__device__ int    g_prefv[SCAN_BLKS];
__device__ int    g_status[SCAN_BLKS];
__device__ float  g_va[7 * 4];        // per-k dot of W1 col-block with a_src/a_dst
__device__ __half g_W2aT[128 * 128];  // fp16 hi part of W2, transposed [N][K]
__device__ __half g_W2bT[128 * 128];  // fp16 residual part, transposed [N][K]
__device__ __half g_h[NPAD * 128];    // transformed features, fp16
__device__ float  g_es[NN * 2];
__device__ float  g_ed[NN * 2];
__device__ __half g_out1[NPAD * 128]; // layer-1 output (relu'd), fp16
__device__ float  g_out2[NN * 64];    // layer-2 output (head mean), fp32

// ---------------- kernel 1: edge count + prep (W2 split/transpose, va, flags) ----------------
__global__ void k_count_prep(const int* __restrict__ ei,
                             const float* __restrict__ W1,
                             const float* __restrict__ as1, const float* __restrict__ ad1,
                             const float* __restrict__ W2) {
    int b = blockIdx.x;
    int t = threadIdx.x;
    if (b < CNT_BLKS) {
        int i = b * 256 + t;
        atomicAdd(&g_deg[ei[NE + i]], 1);  // dst = ei[1][i]
    } else if (b == CNT_BLKS) {
        // W2 -> fp16 hi + fp16 residual, transposed to [N][K]
        for (int idx = t; idx < 128 * 128; idx += 256) {
            int k = idx >> 7, n = idx & 127;
            float w = W2[idx];
            __half a = __float2half_rn(w);
            __half bb = __float2half_rn(w - __half2float(a));
            g_W2aT[n * 128 + k] = a;
            g_W2bT[n * 128 + k] = bb;
        }
    } else {
        // va[k][comp]: comp = {es_h0, es_h1, ed_h0, ed_h1}
        if (t < 28) {
            int k = t >> 2, comp = t & 3;
            int h = comp & 1;
            const float* vec = (comp < 2) ? as1 : ad1;
            float s = 0.f;
#pragma unroll
            for (int c = 0; c < 64; c++) s += W1[k * 128 + h * 64 + c] * vec[h * 64 + c];
            g_va[k * 4 + comp] = s;
        }
        if (t >= 32 && t < 32 + SCAN_BLKS) g_status[t - 32] = 0;  // reset lookback flags
    }
}

// ---------------- kernel 2: single-pass scan (decoupled lookback) ----------------
__global__ void k_scanall() {  // SCAN_BLKS blocks x 256 threads; 4 nodes/thread
    __shared__ int sh[256];
    __shared__ int s_prefix;
    int b = blockIdx.x;
    int t = threadIdx.x;
    int base = b * 1024;
    int idx = base + t * 4;
    int v[4];
    int s = 0;
#pragma unroll
    for (int r = 0; r < 4; r++) {
        v[r] = (idx + r < NN) ? (g_deg[idx + r] + 1) : 0;  // +1 self-loop
        if (idx + r < NN) g_deg[idx + r] = 0;              // restore invariant
        s += v[r];
    }
    sh[t] = s;
    __syncthreads();
    for (int off = 1; off < 256; off <<= 1) {
        int tv = (t >= off) ? sh[t - off] : 0;
        __syncthreads();
        sh[t] += tv;
        __syncthreads();
    }
    int total = sh[255];
    if (t == 0) {
        if (b == 0) {
            g_prefv[0] = total;
            __threadfence();
            ((volatile int*)g_status)[0] = 2;
            s_prefix = 0;
        } else {
            g_aggv[b] = total;
            __threadfence();
            ((volatile int*)g_status)[b] = 1;
            int run = 0;
            int i = b - 1;
            while (true) {
                int st;
                do { st = ((volatile int*)g_status)[i]; } while (st == 0);
                __threadfence();
                if (st == 1) { run += ((volatile int*)g_aggv)[i]; i--; }
                else         { run += ((volatile int*)g_prefv)[i]; break; }
            }
            g_prefv[b] = run + total;
            __threadfence();
            ((volatile int*)g_status)[b] = 2;
            s_prefix = run;
        }
    }
    __syncthreads();
    int excl = s_prefix + sh[t] - s;
#pragma unroll
    for (int r = 0; r < 4; r++) {
        if (idx + r < NN) {
            g_rowptr[idx + r] = excl;
            g_cursor[idx + r] = excl;
            excl += v[r];
            if (idx + r == NN - 1) g_rowptr[NN] = excl;
        }
    }
}

// ---------------- kernel 3: fused scatter + layer-1 transform ----------------
__global__ void k_scatter_transform(const int* __restrict__ ei,
                                    const float* __restrict__ x,
                                    const float* __restrict__ W1) {
    int b = blockIdx.x;
    int t = threadIdx.x;
    if (b < TR_BLKS) {
        __shared__ float sx[16 * 7];
        int nb = b * 16;
        int ch = t & 127;
        int hf = t >> 7;
        float w1r[7];
#pragma unroll
        for (int k = 0; k < 7; k++) w1r[k] = __ldg(&W1[k * 128 + ch]);
        if (t < 112) sx[t] = x[nb * 7 + t];
        __syncthreads();
#pragma unroll
        for (int i = 0; i < 8; i++) {
            int j = hf * 8 + i;
            float acc = 0.f;
#pragma unroll
            for (int k = 0; k < 7; k++) acc += sx[j * 7 + k] * w1r[k];
            g_h[(size_t)(nb + j) * 128 + ch] = __float2half(acc);
        }
        // es/ed: 64 threads, 4 components x 16 nodes, 7-FMA dots with g_va
        if (t < 64) {
            int j = t >> 2, comp = t & 3;
            int n = nb + j;
            float val = 0.f;
#pragma unroll
            for (int k = 0; k < 7; k++) val += sx[j * 7 + k] * g_va[k * 4 + comp];
            if (comp < 2) g_es[2 * n + comp] = val;
            else          g_ed[2 * n + comp - 2] = val;
        }
    } else {
        int i = (b - TR_BLKS) * 256 + t;
        if (i < NE) {
            int s = ei[i], d = ei[NE + i];
            int pos = atomicAdd(&g_cursor[d], 1);
            g_srcs[pos] = s;
        } else if (i < ET) {
            int n = i - NE;
            int pos = atomicAdd(&g_cursor[n], 1);
            g_srcs[pos] = n;
        }
    }
}

// ---------------- segment-softmax + aggregation ----------------
// Warp per node (4 sequential). Lane computes (src, w0, w1) for its edge into
// per-warp smem; broadcast loop (LDS.128, unroll x4) accumulates both the
// weighted features AND the weight sum redundantly in every lane — no warp
// reduction needed for the softmax denominator.
template <int LAYER>
__global__ void __launch_bounds__(256, 6) k_agg(const float* __restrict__ bias) {
    __shared__ float4 sMeta[8][32];
    int wip = threadIdx.x >> 5;
    int gw = (blockIdx.x * blockDim.x + threadIdx.x) >> 5;
    int lane = threadIdx.x & 31;
    int head = lane >> 4;
    float4 bv = make_float4(0.f, 0.f, 0.f, 0.f);
    if (LAYER == 1)      bv = *(const float4*)(bias + lane * 4);
    else if (lane < 16)  bv = *(const float4*)(bias + lane * 4);
    const __half* hlane = g_h + lane * 4;   // lane's 4-channel column base

    for (int q = 0; q < 4; q++) {
        int n = gw * 4 + q;
        int beg = g_rowptr[n], end = g_rowptr[n + 1];
        float2 edv = *(const float2*)(g_ed + 2 * n);

        float sw = 0.f;
        float4 acc = make_float4(0.f, 0.f, 0.f, 0.f);

        for (int base = beg; base < end; base += 32) {
            int j = base + lane;
            float4 meta = make_float4(0.f, 0.f, 0.f, 0.f);
            if (j < end) {
                int src = __ldg(&g_srcs[j]);
                float2 es = *(const float2*)(g_es + 2 * src);
                float e0 = es.x + edv.x; e0 = e0 > 0.f ? e0 : 0.2f * e0;
                float e1 = es.y + edv.y; e1 = e1 > 0.f ? e1 : 0.2f * e1;
                meta = make_float4(__int_as_float(src), __expf(e0), __expf(e1), 0.f);
            }
            sMeta[wip][lane] = meta;
            __syncwarp();

            int cnt = end - base; if (cnt > 32) cnt = 32;
            int jj = 0;
            for (; jj + 4 <= cnt; jj += 4) {
                float4 mA = sMeta[wip][jj];
                float4 mB = sMeta[wip][jj + 1];
                float4 mC = sMeta[wip][jj + 2];
                float4 mD = sMeta[wip][jj + 3];
                float wA = head ? mA.z : mA.y;
                float wB = head ? mB.z : mB.y;
                float wC = head ? mC.z : mC.y;
                float wD = head ? mD.z : mD.y;
                uint2 uA = *(const uint2*)(hlane + (size_t)__float_as_int(mA.x) * 128);
                uint2 uB = *(const uint2*)(hlane + (size_t)__float_as_int(mB.x) * 128);
                uint2 uC = *(const uint2*)(hlane + (size_t)__float_as_int(mC.x) * 128);
                uint2 uD = *(const uint2*)(hlane + (size_t)__float_as_int(mD.x) * 128);
                sw += wA + wB + wC + wD;
                float2 a01 = __half22float2(*(__half2*)&uA.x);
                float2 a23 = __half22float2(*(__half2*)&uA.y);
                float2 b01 = __half22float2(*(__half2*)&uB.x);
                float2 b23 = __half22float2(*(__half2*)&uB.y);
                float2 c01 = __half22float2(*(__half2*)&uC.x);
                float2 c23 = __half22float2(*(__half2*)&uC.y);
                float2 d01 = __half22float2(*(__half2*)&uD.x);
                float2 d23 = __half22float2(*(__half2*)&uD.y);
                acc.x += wA * a01.x + wB * b01.x + wC * c01.x + wD * d01.x;
                acc.y += wA * a01.y + wB * b01.y + wC * c01.y + wD * d01.y;
                acc.z += wA * a23.x + wB * b23.x + wC * c23.x + wD * d23.x;
                acc.w += wA * a23.y + wB * b23.y + wC * c23.y + wD * d23.y;
            }
            for (; jj < cnt; jj++) {
                float4 mA = sMeta[wip][jj];
                float wA = head ? mA.z : mA.y;
                uint2 uA = *(const uint2*)(hlane + (size_t)__float_as_int(mA.x) * 128);
                sw += wA;
                float2 a01 = __half22float2(*(__half2*)&uA.x);
                float2 a23 = __half22float2(*(__half2*)&uA.y);
                acc.x += wA * a01.x; acc.y += wA * a01.y;
                acc.z += wA * a23.x; acc.w += wA * a23.y;
            }
            __syncwarp();
        }

        float invs = 1.f / sw;

        if (LAYER == 1) {
            float4 o;
            o.x = fmaxf(acc.x * invs + bv.x, 0.f);
            o.y = fmaxf(acc.y * invs + bv.y, 0.f);
            o.z = fmaxf(acc.z * invs + bv.z, 0.f);
            o.w = fmaxf(acc.w * invs + bv.w, 0.f);
            __half2 h01 = __floats2half2_rn(o.x, o.y);
            __half2 h23 = __floats2half2_rn(o.z, o.w);
            uint2 u;
            u.x = *(unsigned*)&h01; u.y = *(unsigned*)&h23;
            ((uint2*)(g_out1 + (size_t)n * 128))[lane] = u;
        } else {
            acc.x *= invs; acc.y *= invs; acc.z *= invs; acc.w *= invs;
            acc.x += __shfl_xor_sync(0xffffffffu, acc.x, 16);
            acc.y += __shfl_xor_sync(0xffffffffu, acc.y, 16);
            acc.z += __shfl_xor_sync(0xffffffffu, acc.z, 16);
            acc.w += __shfl_xor_sync(0xffffffffu, acc.w, 16);
            if (lane < 16) {
                float4 o;
                o.x = 0.5f * acc.x + bv.x;
                o.y = 0.5f * acc.y + bv.y;
                o.z = 0.5f * acc.z + bv.z;
                o.w = 0.5f * acc.w + bv.w;
                *(float4*)&g_out2[(size_t)n * 64 + lane * 4] = o;
            }
        }
    }
}

// ---------------- layer 2 GEMM on tensor cores + fused attention scores ----------------
__global__ void k_gemm2(const float* __restrict__ as, const float* __restrict__ ad) {
    __shared__ __half sA[64 * 136];
    __shared__ __half sB[128 * 136];
    __shared__ float  sEs[64][2], sEd[64][2];
    int tid = threadIdx.x;             // 256
    int lane = tid & 31;
    int w = tid >> 5;
    int wm = w >> 1;
    int wn = w & 1;
    int nbase = blockIdx.x * 64;

#pragma unroll
    for (int r = 0; r < 4; r++) {
        int idx = tid + r * 256;
        int row = idx >> 4, c8 = idx & 15;
        uint4 u = ((const uint4*)(g_out1 + (size_t)nbase * 128))[idx];
        *(uint4*)&sA[row * 136 + c8 * 8] = u;
    }

    float acc[8][4];
#pragma unroll
    for (int nt = 0; nt < 8; nt++) { acc[nt][0] = acc[nt][1] = acc[nt][2] = acc[nt][3] = 0.f; }

    int r0 = lane >> 2;
    int kq = (lane & 3) * 2;

    const __half* W2p[2] = {g_W2aT, g_W2bT};
#pragma unroll
    for (int part = 0; part < 2; part++) {
        __syncthreads();
#pragma unroll
        for (int r = 0; r < 8; r++) {
            int idx = tid + r * 256;
            int row = idx >> 4, c8 = idx & 15;
            uint4 u = ((const uint4*)W2p[part])[idx];
            *(uint4*)&sB[row * 136 + c8 * 8] = u;
        }
        __syncthreads();
#pragma unroll
        for (int ks = 0; ks < 8; ks++) {
            int k0 = ks * 16 + kq;
            int arow = wm * 16 + r0;
            unsigned a0 = *(const unsigned*)&sA[arow * 136 + k0];
            unsigned a1 = *(const unsigned*)&sA[(arow + 8) * 136 + k0];
            unsigned a2 = *(const unsigned*)&sA[arow * 136 + k0 + 8];
            unsigned a3 = *(const unsigned*)&sA[(arow + 8) * 136 + k0 + 8];
#pragma unroll
            for (int nt = 0; nt < 8; nt++) {
                int col = wn * 64 + nt * 8 + r0;
                unsigned b0 = *(const unsigned*)&sB[col * 136 + k0];
                unsigned b1 = *(const unsigned*)&sB[col * 136 + k0 + 8];
                asm volatile(
                    "mma.sync.aligned.m16n8k16.row.col.f32.f16.f16.f32 "
                    "{%0,%1,%2,%3}, {%4,%5,%6,%7}, {%8,%9}, {%0,%1,%2,%3};"
                    : "+f"(acc[nt][0]), "+f"(acc[nt][1]), "+f"(acc[nt][2]), "+f"(acc[nt][3])
                    : "r"(a0), "r"(a1), "r"(a2), "r"(a3), "r"(b0), "r"(b1));
            }
        }
    }

    int row = wm * 16 + r0;
    float ps0 = 0.f, ps1 = 0.f, pd0 = 0.f, pd1 = 0.f;
#pragma unroll
    for (int nt = 0; nt < 8; nt++) {
        int colb = wn * 64 + nt * 8 + kq;
        __half2 hlo = __floats2half2_rn(acc[nt][0], acc[nt][1]);
        __half2 hhi = __floats2half2_rn(acc[nt][2], acc[nt][3]);
        *(__half2*)&g_h[(size_t)(nbase + row) * 128 + colb] = hlo;
        *(__half2*)&g_h[(size_t)(nbase + row + 8) * 128 + colb] = hhi;
        float a0v = __ldg(&as[colb]), a1v = __ldg(&as[colb + 1]);
        float d0v = __ldg(&ad[colb]), d1v = __ldg(&ad[colb + 1]);
        ps0 += acc[nt][0] * a0v + acc[nt][1] * a1v;
        ps1 += acc[nt][2] * a0v + acc[nt][3] * a1v;
        pd0 += acc[nt][0] * d0v + acc[nt][1] * d1v;
        pd1 += acc[nt][2] * d0v + acc[nt][3] * d1v;
    }
#pragma unroll
    for (int off = 1; off <= 2; off <<= 1) {
        ps0 += __shfl_xor_sync(0xffffffffu, ps0, off);
        ps1 += __shfl_xor_sync(0xffffffffu, ps1, off);
        pd0 += __shfl_xor_sync(0xffffffffu, pd0, off);
        pd1 += __shfl_xor_sync(0xffffffffu, pd1, off);
    }
    if ((lane & 3) == 0) {
        sEs[row][wn] = ps0; sEs[row + 8][wn] = ps1;
        sEd[row][wn] = pd0; sEd[row + 8][wn] = pd1;
    }
    __syncthreads();
    if (tid < 64) {
        int n = nbase + tid;
        if (n < NN) {
            *(float2*)&g_es[2 * n] = make_float2(sEs[tid][0], sEs[tid][1]);
            *(float2*)&g_ed[2 * n] = make_float2(sEd[tid][0], sEd[tid][1]);
        }
    }
}

// ---------------- classifier: relu(out2@Wc1+bc1)@Wc2+bc2 -> d_out ----------------
__global__ void k_classifier(const float* __restrict__ Wc1, const float* __restrict__ bc1,
                             const float* __restrict__ Wc2, const float* __restrict__ bc2,
                             float* __restrict__ out) {
    __shared__ float sW1[64 * 64];
    __shared__ float sW2[64 * 4];
    __shared__ float sb1[64];
    __shared__ float sb2[4];
    __shared__ float sv[16 * 64];
    __shared__ float sh2[16 * 64];
    int tid = threadIdx.x;          // 256
    int nbase = blockIdx.x * 16;

#pragma unroll
    for (int r = 0; r < 4; r++)
        ((float4*)sW1)[tid + r * 256] = ((const float4*)Wc1)[tid + r * 256];
    if (tid < 64) {
        ((float4*)sW2)[tid] = ((const float4*)Wc2)[tid];
        sb1[tid] = bc1[tid];
    }
    if (tid < 4) sb2[tid] = bc2[tid];
    ((float4*)sv)[tid] = ((const float4*)(g_out2 + (size_t)nbase * 64))[tid];
    __syncthreads();

    {
        int node = tid >> 4;
        int cq = tid & 15;
        float a0 = sb1[cq * 4], a1 = sb1[cq * 4 + 1], a2 = sb1[cq * 4 + 2], a3 = sb1[cq * 4 + 3];
#pragma unroll
        for (int k = 0; k < 64; k++) {
            float v = sv[node * 64 + k];
            float4 wv = *(float4*)&sW1[k * 64 + cq * 4];
            a0 += v * wv.x; a1 += v * wv.y; a2 += v * wv.z; a3 += v * wv.w;
        }
        *(float4*)&sh2[node * 64 + cq * 4] =
            make_float4(fmaxf(a0, 0.f), fmaxf(a1, 0.f), fmaxf(a2, 0.f), fmaxf(a3, 0.f));
    }
    __syncthreads();

    if (tid < 64) {
        int n2 = tid >> 2, o = tid & 3;
        float a = sb2[o];
#pragma unroll
        for (int k = 0; k < 64; k++) a += sh2[n2 * 64 + k] * sW2[k * 4 + o];
        out[(size_t)(nbase + n2) * 4 + o] = a;
    }
}

// ---------------- launch ----------------
extern "C" void kernel_launch(void* const* d_in, const int* in_sizes, int n_in,
                              void* d_out, int out_size) {
    const float* x   = (const float*)d_in[0];
    const int*   ei  = (const int*)d_in[1];
    const float* W1  = (const float*)d_in[2];
    const float* as1 = (const float*)d_in[3];
    const float* ad1 = (const float*)d_in[4];
    const float* b1  = (const float*)d_in[5];
    const float* W2  = (const float*)d_in[6];
    const float* as2 = (const float*)d_in[7];
    const float* ad2 = (const float*)d_in[8];
    const float* b2  = (const float*)d_in[9];
    const float* Wc1 = (const float*)d_in[10];
    const float* bc1 = (const float*)d_in[11];
    const float* Wc2 = (const float*)d_in[12];
    const float* bc2 = (const float*)d_in[13];
    float* out = (float*)d_out;

    k_count_prep<<<CNT_BLKS + 2, 256>>>(ei, W1, as1, ad1, W2);          // 1
    k_scanall<<<SCAN_BLKS, 256>>>();                                    // 2
    k_scatter_transform<<<TR_BLKS + SC_BLKS, 256>>>(ei, x, W1);         // 3
    k_agg<1><<<NN / 32, 256>>>(b1);                                     // 4 (profiled)
    k_gemm2<<<NPAD / 64, 256>>>(as2, ad2);                              // 5
    k_agg<2><<<NN / 32, 256>>>(b2);                                     // 6
    k_classifier<<<NN / 16, 256>>>(Wc1, bc1, Wc2, bc2, out);            // 7
}